// round 8
// baseline (speedup 1.0000x reference)
#include <cuda_runtime.h>
#include <cuda_bf16.h>
#include <math.h>
#include <stdint.h>

// ---------------------------------------------------------------------------
// Problem constants
// ---------------------------------------------------------------------------
#define HH 64
#define WW 64
#define HWSZ 4096
#define CIN 128
#define TT 4
#define DM 256
#define NQ 300
#define NP 8
#define NLAY 6
#define BATCH 2
#define MROWS (BATCH*HWSZ)      // 8192 spatial rows
#define MQ (BATCH*NQ)           // 600 query rows
#define MS (MQ*NP)              // 4800 sample rows
#define KP1 2304                // 3*3*256

// ---------------------------------------------------------------------------
// Scratch
// ---------------------------------------------------------------------------
constexpr size_t O_WCOMB = 0;                        // 256*512
constexpr size_t O_BCOMB = O_WCOMB + 256*512;        // 256
constexpr size_t O_PY    = O_BCOMB + 256;            // 64*128
constexpr size_t O_PX    = O_PY + 64*128;            // 64*128 (contiguous after PY)
constexpr size_t O_WSMP  = O_PX + 64*128;            // 256*2304 permuted w_sm
constexpr size_t O_X     = O_WSMP + (size_t)DM*KP1;  // 8192*256
constexpr size_t O_LAT   = O_X + (size_t)MROWS*DM;   // 8192*256
constexpr size_t O_F0    = O_LAT + (size_t)MROWS*DM; // 8192*256
constexpr size_t O_Q     = O_F0 + (size_t)MROWS*DM;  // 600*256
constexpr size_t O_H1    = O_Q + MQ*DM;
constexpr size_t O_REF   = O_H1 + MQ*DM;             // 600*8*2
constexpr size_t O_PV    = O_REF + MQ*NP*2;          // 4800*256
constexpr size_t O_KV    = O_PV + (size_t)MS*DM;
constexpr size_t O_QP    = O_KV + MQ*DM;
constexpr size_t O_KVT   = O_QP + MQ*DM;             // 2*256*300
constexpr size_t O_S     = O_KVT + MQ*DM;            // 2*300*300
constexpr size_t O_AO    = O_S + BATCH*NQ*NQ;
constexpr size_t O_HB    = O_AO + MQ*DM;
constexpr size_t O_BOX   = O_HB + MQ*DM;             // 600*4
constexpr size_t G_TOTAL = O_BOX + MQ*4;

__device__ float g_buf[G_TOTAL];

// ---------------------------------------------------------------------------
// BF16 split helpers
// ---------------------------------------------------------------------------
__device__ __forceinline__ void split_bf16(float x, float& hf, float& lf) {
  __nv_bfloat16 h = __float2bfloat16(x);
  hf = __bfloat162float(h);
  lf = x - hf;
}
__device__ __forceinline__ uint32_t pack_bf16(float lo_elem, float hi_elem) {
  __nv_bfloat162 t = __floats2bfloat162_rn(lo_elem, hi_elem);
  return *reinterpret_cast<uint32_t*>(&t);
}
__device__ __forceinline__ void mma_bf16(float* c, const uint32_t* a, const uint32_t* b) {
  asm volatile(
    "mma.sync.aligned.m16n8k16.row.col.f32.bf16.bf16.f32 "
    "{%0,%1,%2,%3},{%4,%5,%6,%7},{%8,%9},{%0,%1,%2,%3};"
    : "+f"(c[0]), "+f"(c[1]), "+f"(c[2]), "+f"(c[3])
    : "r"(a[0]), "r"(a[1]), "r"(a[2]), "r"(a[3]), "r"(b[0]), "r"(b[1]));
}

// ---------------------------------------------------------------------------
// 3xBF16 GEMM (Karatsuba hi/lo). Block 128x64, 8 warps of 32x32, BK=32,
// double-buffered 48KB dynamic smem, fragment-layout + XOR swizzle.
// GATHER: 0 = plain A[M,K]
//         1 = im2col of (b,64,64,256) channel-last map ([ky][kx][c] K-order)
//         2 = stem gather from feat[b][t][i][hw], k=i*4+t (coalesced over hw)
//         3 = bilinear patch sampling from f0 (aux = ref points)
//         4 = mean over 8 point-rows of A
// EPI: 0=+bias, 1=+bias+relu, 2=+bias+res, 3=+bias+sinepos(aux)
// ---------------------------------------------------------------------------
template<int EPI, int GATHER>
__global__ __launch_bounds__(256, 2)
void gemm_b16(const float* __restrict__ A, const float* __restrict__ Bw,
              const float* __restrict__ bias, const float* __restrict__ res,
              const float* __restrict__ aux, float* __restrict__ C,
              int M, int N, int K,
              long long sA, long long sB, long long sC) {
  const int BM = 128, BN = 64, BK = 32;
  extern __shared__ uint32_t smem[];
  uint32_t* SAb = smem;            // 2 x 4096 words
  uint32_t* SBb = smem + 8192;     // 2 x 2048 words

  A  += blockIdx.z * sA;
  Bw += blockIdx.z * sB;
  C  += blockIdx.z * sC;

  int tid = threadIdx.x;
  int bm = blockIdx.y * BM, bn = blockIdx.x * BN;
  int lane = tid & 31, warp = tid >> 5;
  int wm = (warp >> 1) * 32, wn = (warp & 1) * 32;
  int gid = lane >> 2, tig = lane & 3;
  int xr = (lane >> 2) & 7;

  float acc[2][4][4] = {};
  int Kpad = (K + BK - 1) / BK * BK;

  int am4[4], ak4[4], bn2[2], bk2[2];
  #pragma unroll
  for (int l = 0; l < 4; ++l) {
    int li = tid + l * 256;
    am4[l] = li >> 3;
    ak4[l] = (li & 7) * 4;
  }
  #pragma unroll
  for (int l = 0; l < 2; ++l) {
    int li = tid + l * 256;
    bn2[l] = li >> 3;
    bk2[l] = (li & 7) * 4;
  }
  // GATHER==2 fill mapping: thread -> (m2, khalf), 16 scalar loads
  int m2 = tid & 127, khalf = tid >> 7;

  float4 pa[4], pb[2];
  float pa2[16];

  auto loadA = [&](int k0, int l) -> float4 {
    float4 v = make_float4(0.f, 0.f, 0.f, 0.f);
    int gm = bm + am4[l], gk = k0 + ak4[l];
    if (GATHER == 1) {
      if (gm < M && gk < K) {
        int ky = gk / 768, rem = gk - ky * 768;
        int kx = rem >> 8, c = rem & 255;
        int b = gm >> 12, hw = gm & 4095, h = hw >> 6, w = hw & 63;
        int hh = h + ky - 1, ww = w + kx - 1;
        if (hh >= 0 && hh < 64 && ww >= 0 && ww < 64)
          v = *reinterpret_cast<const float4*>(A + ((size_t)(b << 12) + (hh << 6) + ww) * 256 + c);
      }
    } else if (GATHER == 3) {
      // bilinear patch sampling; A = f0 (b,64,64,256), aux = ref[4800][2]
      if (gm < M && gk < K) {
        int kk = gk >> 8, c = gk & 255;
        int m = gm >> 3;
        int b = (m >= NQ) ? 1 : 0;
        float rx = aux[gm * 2 + 0];
        float ry = aux[gm * 2 + 1];
        float ox = (float)(kk % 3 - 1), oy = (float)(kk / 3 - 1);
        float x = fminf(fmaxf((rx + ox * (1.f / 64.f)) * 63.f, 0.f), 63.f);
        float y = fminf(fmaxf((ry + oy * (1.f / 64.f)) * 63.f, 0.f), 63.f);
        float x0 = floorf(x), y0 = floorf(y);
        float wx = x - x0, wy = y - y0;
        int x0i = (int)x0, y0i = (int)y0;
        int x1i = min(x0i + 1, 63), y1i = min(y0i + 1, 63);
        const float* f = A + (size_t)b * HWSZ * DM;
        float4 v00 = *reinterpret_cast<const float4*>(f + ((y0i << 6) + x0i) * DM + c);
        float4 v01 = *reinterpret_cast<const float4*>(f + ((y0i << 6) + x1i) * DM + c);
        float4 v10 = *reinterpret_cast<const float4*>(f + ((y1i << 6) + x0i) * DM + c);
        float4 v11 = *reinterpret_cast<const float4*>(f + ((y1i << 6) + x1i) * DM + c);
        float w00 = (1.f - wx) * (1.f - wy), w01 = wx * (1.f - wy);
        float w10 = (1.f - wx) * wy,         w11 = wx * wy;
        v.x = v00.x * w00 + v01.x * w01 + v10.x * w10 + v11.x * w11;
        v.y = v00.y * w00 + v01.y * w01 + v10.y * w10 + v11.y * w11;
        v.z = v00.z * w00 + v01.z * w01 + v10.z * w10 + v11.z * w11;
        v.w = v00.w * w00 + v01.w * w01 + v10.w * w10 + v11.w * w11;
      }
    } else if (GATHER == 4) {
      // mean over 8 point rows: A row (gm*8+p)
      if (gm < M) {
        const float* base = A + ((size_t)gm * 8) * DM + gk;
        float4 s = make_float4(0.f, 0.f, 0.f, 0.f);
        #pragma unroll
        for (int p = 0; p < 8; ++p) {
          float4 t = *reinterpret_cast<const float4*>(base + (size_t)p * DM);
          s.x += t.x; s.y += t.y; s.z += t.z; s.w += t.w;
        }
        v = make_float4(s.x * 0.125f, s.y * 0.125f, s.z * 0.125f, s.w * 0.125f);
      }
    } else {
      if (gm < M) {
        if (gk + 3 < K) v = *reinterpret_cast<const float4*>(A + (size_t)gm * K + gk);
        else {
          float t[4] = {0.f, 0.f, 0.f, 0.f};
          #pragma unroll
          for (int e = 0; e < 4; ++e) if (gk + e < K) t[e] = A[(size_t)gm * K + gk + e];
          v = make_float4(t[0], t[1], t[2], t[3]);
        }
      }
    }
    return v;
  };
  auto loadB = [&](int k0, int l) -> float4 {
    float4 v = make_float4(0.f, 0.f, 0.f, 0.f);
    int gn = bn + bn2[l], gk = k0 + bk2[l];
    if (gn < N) {
      if (gk + 3 < K) v = *reinterpret_cast<const float4*>(Bw + (size_t)gn * K + gk);
      else {
        float t[4] = {0.f, 0.f, 0.f, 0.f};
        #pragma unroll
        for (int e = 0; e < 4; ++e) if (gk + e < K) t[e] = Bw[(size_t)gn * K + gk + e];
        v = make_float4(t[0], t[1], t[2], t[3]);
      }
    }
    return v;
  };
  auto prefetch = [&](int k0) {
    if (GATHER == 2) {
      // stem: feat[b][t][i][hw], k = i*4+t; coalesced over hw
      int gm = bm + m2;
      int b = gm >> 12, hw = gm & 4095;
      #pragma unroll
      for (int j = 0; j < 16; ++j) {
        int k = k0 + khalf * 16 + j;
        int i = k >> 2, t = k & 3;
        pa2[j] = A[(size_t)(((b << 2) + t) * CIN + i) * HWSZ + hw];
      }
    } else {
      #pragma unroll
      for (int l = 0; l < 4; ++l) pa[l] = loadA(k0, l);
    }
    #pragma unroll
    for (int l = 0; l < 2; ++l) pb[l] = loadB(k0, l);
  };

  auto storeTiles = [&](int buf) {
    uint32_t* SA = SAb + buf * 4096;
    uint32_t* SB = SBb + buf * 2048;
    if (GATHER == 2) {
      int tm = m2 >> 4, rr = m2 & 15;
      #pragma unroll
      for (int j = 0; j < 8; ++j) {
        int k16p = 2 * j;
        int lw = (rr & 7) * 4 + (j & 3);
        int reg = (rr >> 3) | ((j >> 2) << 1);
        float h0, l0, h1, l1;
        split_bf16(pa2[2 * j], h0, l0);
        split_bf16(pa2[2 * j + 1], h1, l1);
        int s0 = (((tm * 2 + khalf) * 32 + lw) * 2) ^ ((lw >> 2) & 7);
        SA[s0 * 4 + reg]       = pack_bf16(h0, h1);
        SA[(s0 ^ 1) * 4 + reg] = pack_bf16(l0, l1);
      }
    } else {
      #pragma unroll
      for (int l = 0; l < 4; ++l) {
        float v[4] = {pa[l].x, pa[l].y, pa[l].z, pa[l].w};
        int tm = am4[l] >> 4, rr = am4[l] & 15;
        int tk = ak4[l] >> 4, k16b = ak4[l] & 15;
        #pragma unroll
        for (int e = 0; e < 2; ++e) {
          int k16p = k16b + 2 * e;
          int lw = (rr & 7) * 4 + ((k16p >> 1) & 3);
          int reg = (rr >> 3) | ((k16p >> 3) << 1);
          float h0, l0, h1, l1;
          split_bf16(v[2 * e], h0, l0);
          split_bf16(v[2 * e + 1], h1, l1);
          int s0 = (((tm * 2 + tk) * 32 + lw) * 2) ^ ((lw >> 2) & 7);
          SA[s0 * 4 + reg]       = pack_bf16(h0, h1);
          SA[(s0 ^ 1) * 4 + reg] = pack_bf16(l0, l1);
        }
      }
    }
    #pragma unroll
    for (int l = 0; l < 2; ++l) {
      float v[4] = {pb[l].x, pb[l].y, pb[l].z, pb[l].w};
      int ntile = bn2[l] >> 3, gidn = bn2[l] & 7;
      int np = ntile >> 1, nodd = ntile & 1;
      int tk = bk2[l] >> 4, k16b = bk2[l] & 15;
      #pragma unroll
      for (int e = 0; e < 2; ++e) {
        int k16p = k16b + 2 * e;
        int lw = gidn * 4 + ((k16p >> 1) & 3);
        int reg = k16p >> 3;
        int word = nodd * 2 + reg;
        float h0, l0, h1, l1;
        split_bf16(v[2 * e], h0, l0);
        split_bf16(v[2 * e + 1], h1, l1);
        int s0 = (((np * 2 + tk) * 32 + lw) * 2) ^ ((lw >> 2) & 7);
        SB[s0 * 4 + word]       = pack_bf16(h0, h1);
        SB[(s0 ^ 1) * 4 + word] = pack_bf16(l0, l1);
      }
    }
  };

  prefetch(0);
  storeTiles(0);
  if (BK < Kpad) prefetch(BK);
  __syncthreads();

  int cur = 0;
  for (int k0 = 0; k0 < Kpad; k0 += BK) {
    if (k0 + BK < Kpad) {
      storeTiles(cur ^ 1);
      if (k0 + 2 * BK < Kpad) prefetch(k0 + 2 * BK);
    }
    const uint32_t* SA = SAb + cur * 4096;
    const uint32_t* SB = SBb + cur * 2048;
    #pragma unroll
    for (int tk = 0; tk < 2; ++tk) {
      uint32_t Ahf[2][4], Alf[2][4];
      #pragma unroll
      for (int i = 0; i < 2; ++i) {
        int tm = (wm >> 4) + i;
        int s0 = (((tm * 2 + tk) * 32 + lane) * 2) ^ xr;
        *reinterpret_cast<uint4*>(Ahf[i]) = *reinterpret_cast<const uint4*>(&SA[s0 * 4]);
        *reinterpret_cast<uint4*>(Alf[i]) = *reinterpret_cast<const uint4*>(&SA[(s0 ^ 1) * 4]);
      }
      uint32_t Bhf[2][4], Blf[2][4];
      #pragma unroll
      for (int jp = 0; jp < 2; ++jp) {
        int np = (wn >> 4) + jp;
        int s0 = (((np * 2 + tk) * 32 + lane) * 2) ^ xr;
        *reinterpret_cast<uint4*>(Bhf[jp]) = *reinterpret_cast<const uint4*>(&SB[s0 * 4]);
        *reinterpret_cast<uint4*>(Blf[jp]) = *reinterpret_cast<const uint4*>(&SB[(s0 ^ 1) * 4]);
      }
      #pragma unroll
      for (int i = 0; i < 2; ++i)
        #pragma unroll
        for (int jp = 0; jp < 2; ++jp)
          #pragma unroll
          for (int nodd = 0; nodd < 2; ++nodd) {
            int j = jp * 2 + nodd;
            uint32_t bh[2] = {Bhf[jp][nodd * 2], Bhf[jp][nodd * 2 + 1]};
            uint32_t bl[2] = {Blf[jp][nodd * 2], Blf[jp][nodd * 2 + 1]};
            mma_bf16(acc[i][j], Ahf[i], bh);
            mma_bf16(acc[i][j], Ahf[i], bl);
            mma_bf16(acc[i][j], Alf[i], bh);
          }
    }
    __syncthreads();
    cur ^= 1;
  }

  #pragma unroll
  for (int i = 0; i < 2; ++i) {
    #pragma unroll
    for (int j = 0; j < 4; ++j) {
      int c0 = bn + wn + 8 * j + 2 * tig;
      #pragma unroll
      for (int half = 0; half < 2; ++half) {
        int gm = bm + wm + 16 * i + gid + 8 * half;
        if (gm >= M) continue;
        #pragma unroll
        for (int e = 0; e < 2; ++e) {
          int gn = c0 + e;
          if (gn >= N) continue;
          float v = acc[i][j][half * 2 + e] + (bias ? bias[gn] : 0.f);
          if (EPI == 1) v = fmaxf(v, 0.f);
          if (EPI == 2) v += res[(size_t)gm * N + gn];
          if (EPI == 3) {
            int hw = gm & 4095, h = hw >> 6, w = hw & 63;
            v += (gn < 128) ? aux[h * 128 + gn] : aux[8192 + w * 128 + (gn - 128)];
          }
          C[(size_t)gm * N + gn] = v;
        }
      }
    }
  }
}

// ---------------------------------------------------------------------------
// Permute w_sm [o][c][ky][kx] -> [o][ky][kx][c]
// ---------------------------------------------------------------------------
__global__ __launch_bounds__(256)
void k_wsmperm(const float* __restrict__ w_sm, float* __restrict__ out) {
  int idx = blockIdx.x * 256 + threadIdx.x;
  if (idx >= DM * KP1) return;
  int o = idx / KP1, r = idx - o * KP1;
  int ky = r / 768, rem = r - ky * 768;
  int kx = rem >> 8, c = rem & 255;
  out[idx] = w_sm[(size_t)o * KP1 + c * 9 + ky * 3 + kx];
}

// ---------------------------------------------------------------------------
// Stem weight combine
// ---------------------------------------------------------------------------
__global__ __launch_bounds__(256)
void k_wcomb(const float* __restrict__ w_tf, const float* __restrict__ w_in,
             const float* __restrict__ b_tf, const float* __restrict__ b_in,
             float* __restrict__ wcomb, float* __restrict__ bcomb) {
  int idx = blockIdx.x * 256 + threadIdx.x;
  if (idx < 256 * 512) {
    int dm = idx >> 9, k = idx & 511, i = k >> 2, t = k & 3;
    float s = 0.f;
    for (int c = 0; c < CIN; ++c) {
      const float* wt = w_tf + (c * CIN + i) * 3;
      float we = wt[1];
      if (t != 3) we += wt[0];
      if (t != 0) we += wt[2];
      s += w_in[dm * CIN + c] * we;
    }
    wcomb[idx] = 0.25f * s;
  }
  if (idx < 256) {
    float s = b_in[idx];
    for (int c = 0; c < CIN; ++c) s += w_in[idx * CIN + c] * b_tf[c];
    bcomb[idx] = s;
  }
}

__global__ __launch_bounds__(256)
void k_pos(float* __restrict__ py, float* __restrict__ px) {
  int idx = blockIdx.x * 256 + threadIdx.x;
  if (idx >= 2 * 64 * 128) return;
  int half = idx / (64 * 128);
  int r = idx - half * (64 * 128);
  int hw = r >> 7, c = r & 127;
  float dim_t = powf(10000.f, 2.f * (float)(c >> 2) / 64.f);
  float v = (float)(hw + 1) / (64.f + 1e-6f) * 2.f * 3.14159265358979323846f;
  float a = v / dim_t;
  float o = (c & 1) ? cosf(a) : sinf(a);
  if (half) px[r] = o; else py[r] = o;
}

__global__ __launch_bounds__(256)
void k_qinit(const float* __restrict__ q_embed, const float* __restrict__ q_pos,
             const float* __restrict__ boxes0, float* __restrict__ queries,
             float* __restrict__ boxes) {
  int m = blockIdx.x;
  int q = m % NQ;
  int d = threadIdx.x;
  queries[m * DM + d] = q_embed[q * DM + d] + q_pos[q * DM + d];
  if (d < 4) boxes[m * 4 + d] = boxes0[m * 4 + d];
}

__global__ __launch_bounds__(256)
void k_refpts(const float* __restrict__ h1, const float* __restrict__ boxes,
              const float* __restrict__ w_r2, const float* __restrict__ b_r2,
              float* __restrict__ ref) {
  int m = blockIdx.x;
  int g = threadIdx.x >> 4;
  int lane16 = threadIdx.x & 15;
  float s = 0.f;
  for (int d = lane16; d < DM; d += 16)
    s += h1[m * DM + d] * w_r2[g * DM + d];
  #pragma unroll
  for (int off = 8; off > 0; off >>= 1)
    s += __shfl_down_sync(0xffffffffu, s, off, 16);
  __shared__ float ro_s[16];
  if (lane16 == 0) ro_s[g] = tanhf(s + b_r2[g]) * 0.5f;
  __syncthreads();
  if (threadIdx.x < 16) {
    int p = threadIdx.x >> 1, j = threadIdx.x & 1;
    float v = boxes[m * 4 + j] + ro_s[p * 2 + j];
    ref[(m * NP + p) * 2 + j] = fminf(fmaxf(v, 0.f), 1.f);
  }
}

__global__ __launch_bounds__(256)
void k_kvT(const float* __restrict__ kv, float* __restrict__ kvT) {
  int m = blockIdx.x;
  int b = (m >= NQ) ? 1 : 0;
  int k = m - b * NQ;
  int d = threadIdx.x;
  kvT[((size_t)b * DM + d) * NQ + k] = kv[(size_t)m * DM + d];
}

__global__ __launch_bounds__(512)
void k_softmax(float* __restrict__ S) {
  int m = blockIdx.x;
  int b = (m >= NQ) ? 1 : 0;
  float* row = S + (size_t)b * NQ * NQ + (size_t)(m - b * NQ) * NQ;
  int t = threadIdx.x;
  __shared__ float red[512];
  float v = (t < NQ) ? row[t] * 0.0625f : -1e30f;
  red[t] = v; __syncthreads();
  for (int s = 256; s > 0; s >>= 1) { if (t < s) red[t] = fmaxf(red[t], red[t + s]); __syncthreads(); }
  float mx = red[0]; __syncthreads();
  float e = (t < NQ) ? expf(v - mx) : 0.f;
  red[t] = e; __syncthreads();
  for (int s = 256; s > 0; s >>= 1) { if (t < s) red[t] += red[t + s]; __syncthreads(); }
  float inv = 1.f / red[0];
  if (t < NQ) row[t] = e * inv;
}

__global__ __launch_bounds__(128)
void k_box(const float* __restrict__ hb, const float* __restrict__ w_b2,
           const float* __restrict__ b_b2, float* __restrict__ boxes) {
  int m = blockIdx.x;
  int wj = threadIdx.x >> 5, lane = threadIdx.x & 31;
  float s = 0.f;
  for (int d = lane; d < DM; d += 32) s += hb[m * DM + d] * w_b2[wj * DM + d];
  #pragma unroll
  for (int off = 16; off > 0; off >>= 1) s += __shfl_down_sync(0xffffffffu, s, off);
  if (lane == 0) {
    float delta = 1.f / (1.f + expf(-(s + b_b2[wj])));
    float nb = boxes[m * 4 + wj] + 0.1f * tanhf(delta - 0.5f);
    boxes[m * 4 + wj] = fminf(fmaxf(nb, 0.f), 1.f);
  }
}

__global__ __launch_bounds__(256)
void k_logits(const float* __restrict__ queries, const float* __restrict__ w_cls,
              const float* __restrict__ b_cls, float* __restrict__ out) {
  int m = blockIdx.x, t = threadIdx.x;
  __shared__ float red[256];
  red[t] = queries[m * DM + t] * w_cls[t];
  __syncthreads();
  for (int s = 128; s > 0; s >>= 1) { if (t < s) red[t] += red[t + s]; __syncthreads(); }
  if (t == 0) out[m] = red[0] + b_cls[0];
}

__global__ __launch_bounds__(256)
void k_copyboxes(const float* __restrict__ boxes, float* __restrict__ out) {
  int i = blockIdx.x * 256 + threadIdx.x;
  if (i < MQ * 4) out[MQ + i] = boxes[i];
}

// ---------------------------------------------------------------------------
static inline dim3 ggrid(int M, int N, int Z = 1) {
  return dim3((N + 63) / 64, (M + 127) / 128, Z);
}
#define GSMEM 49152

extern "C" void kernel_launch(void* const* d_in, const int* in_sizes, int n_in,
                              void* d_out, int out_size) {
  const float* feat   = (const float*)d_in[0];
  const float* boxes0 = (const float*)d_in[1];
  const float* w_tf   = (const float*)d_in[2];
  const float* b_tf   = (const float*)d_in[3];
  const float* w_in   = (const float*)d_in[4];
  const float* b_in   = (const float*)d_in[5];
  const float* w_lat  = (const float*)d_in[6];
  const float* b_lat  = (const float*)d_in[7];
  const float* w_sm   = (const float*)d_in[8];
  const float* b_sm   = (const float*)d_in[9];
  const float* q_embed= (const float*)d_in[10];
  const float* q_pos  = (const float*)d_in[11];
  const float* Wq     = (const float*)d_in[12];
  const float* bq     = (const float*)d_in[13];
  const float* Wo     = (const float*)d_in[14];
  const float* bo     = (const float*)d_in[15];
  const float* Wp1    = (const float*)d_in[16];
  const float* bp1    = (const float*)d_in[17];
  const float* Wp2    = (const float*)d_in[18];
  const float* bp2    = (const float*)d_in[19];
  const float* w_r1   = (const float*)d_in[20];
  const float* b_r1   = (const float*)d_in[21];
  const float* w_r2   = (const float*)d_in[22];
  const float* b_r2   = (const float*)d_in[23];
  const float* w_b1   = (const float*)d_in[24];
  const float* b_b1   = (const float*)d_in[25];
  const float* w_b2   = (const float*)d_in[26];
  const float* b_b2   = (const float*)d_in[27];
  const float* w_cls  = (const float*)d_in[28];
  const float* b_cls  = (const float*)d_in[29];
  float* out = (float*)d_out;

  static bool attr_done = false;
  if (!attr_done) {
    cudaFuncSetAttribute(gemm_b16<0,0>, cudaFuncAttributeMaxDynamicSharedMemorySize, GSMEM);
    cudaFuncSetAttribute(gemm_b16<1,0>, cudaFuncAttributeMaxDynamicSharedMemorySize, GSMEM);
    cudaFuncSetAttribute(gemm_b16<2,0>, cudaFuncAttributeMaxDynamicSharedMemorySize, GSMEM);
    cudaFuncSetAttribute(gemm_b16<0,1>, cudaFuncAttributeMaxDynamicSharedMemorySize, GSMEM);
    cudaFuncSetAttribute(gemm_b16<3,2>, cudaFuncAttributeMaxDynamicSharedMemorySize, GSMEM);
    cudaFuncSetAttribute(gemm_b16<1,3>, cudaFuncAttributeMaxDynamicSharedMemorySize, GSMEM);
    cudaFuncSetAttribute(gemm_b16<0,4>, cudaFuncAttributeMaxDynamicSharedMemorySize, GSMEM);
    attr_done = true;
  }

  float* base = nullptr;
  cudaGetSymbolAddress((void**)&base, g_buf);
  float* p_wcomb = base + O_WCOMB;
  float* p_bcomb = base + O_BCOMB;
  float* p_py    = base + O_PY;     // px contiguous at +8192
  float* p_px    = base + O_PX;
  float* p_wsmp  = base + O_WSMP;
  float* p_x     = base + O_X;
  float* p_lat   = base + O_LAT;
  float* p_f0    = base + O_F0;
  float* p_q     = base + O_Q;
  float* p_h1    = base + O_H1;
  float* p_ref   = base + O_REF;
  float* p_pv    = base + O_PV;
  float* p_kv    = base + O_KV;
  float* p_qp    = base + O_QP;
  float* p_kvT   = base + O_KVT;
  float* p_S     = base + O_S;
  float* p_ao    = base + O_AO;
  float* p_hb    = base + O_HB;
  float* p_box   = base + O_BOX;

  // ---- prologue: weights + pos tables ----
  k_wcomb<<<(256 * 512 + 255) / 256, 256>>>(w_tf, w_in, b_tf, b_in, p_wcomb, p_bcomb);
  k_pos<<<(2 * 64 * 128 + 255) / 256, 256>>>(p_py, p_px);
  k_wsmperm<<<(DM * KP1 + 255) / 256, 256>>>(w_sm, p_wsmp);

  // ---- stem: fused conv3d+mean_T+in-proj GEMM on tensor cores, +pos epi ----
  gemm_b16<3,2><<<ggrid(MROWS, DM), 256, GSMEM>>>(feat, p_wcomb, p_bcomb, nullptr, p_py,
                                                  p_x, MROWS, DM, 512, 0, 0, 0);

  // ---- scale-1 feature (scales 2,4 dead in reference) ----
  gemm_b16<0,0><<<ggrid(MROWS, DM), 256, GSMEM>>>(p_x, w_lat, b_lat, nullptr, nullptr,
                                                  p_lat, MROWS, DM, DM, 0, 0, 0);
  gemm_b16<0,1><<<ggrid(MROWS, DM), 256, GSMEM>>>(p_lat, p_wsmp, b_sm, nullptr, nullptr,
                                                  p_f0, MROWS, DM, KP1, 0, 0, 0);

  // ---- decoder init ----
  k_qinit<<<MQ, 256>>>(q_embed, q_pos, boxes0, p_q, p_box);

  for (int l = 0; l < NLAY; ++l) {
    const float* Wq_l  = Wq  + (size_t)l * DM * DM;
    const float* bq_l  = bq  + (size_t)l * DM;
    const float* Wo_l  = Wo  + (size_t)l * DM * DM;
    const float* bo_l  = bo  + (size_t)l * DM;
    const float* Wp1_l = Wp1 + (size_t)l * DM * KP1;
    const float* bp1_l = bp1 + (size_t)l * DM;
    const float* Wp2_l = Wp2 + (size_t)l * DM * DM;
    const float* bp2_l = bp2 + (size_t)l * DM;

    gemm_b16<1,0><<<ggrid(MQ, DM), 256, GSMEM>>>(p_q, w_r1, b_r1, nullptr, nullptr,
                                                 p_h1, MQ, DM, DM, 0, 0, 0);
    k_refpts<<<MQ, 256>>>(p_h1, p_box, w_r2, b_r2, p_ref);

    // patch MLP: bilinear sampling fused into the A-loader (aux = ref)
    gemm_b16<1,3><<<ggrid(MS, DM), 256, GSMEM>>>(p_f0, Wp1_l, bp1_l, nullptr, p_ref,
                                                 p_pv, MS, DM, KP1, 0, 0, 0);
    // Wp2 with fused mean-over-points A-loader
    gemm_b16<0,4><<<ggrid(MQ, DM), 256, GSMEM>>>(p_pv, Wp2_l, bp2_l, nullptr, nullptr,
                                                 p_kv, MQ, DM, DM, 0, 0, 0);

    gemm_b16<0,0><<<ggrid(MQ, DM), 256, GSMEM>>>(p_q, Wq_l, bq_l, nullptr, nullptr,
                                                 p_qp, MQ, DM, DM, 0, 0, 0);
    k_kvT<<<MQ, 256>>>(p_kv, p_kvT);
    gemm_b16<0,0><<<ggrid(NQ, NQ, BATCH), 256, GSMEM>>>(p_qp, p_kv, nullptr, nullptr, nullptr, p_S,
                                                        NQ, NQ, DM,
                                                        (long long)NQ * DM, (long long)NQ * DM,
                                                        (long long)NQ * NQ);
    k_softmax<<<MQ, 512>>>(p_S);
    gemm_b16<0,0><<<ggrid(NQ, DM, BATCH), 256, GSMEM>>>(p_S, p_kvT, nullptr, nullptr, nullptr, p_ao,
                                                        NQ, DM, NQ,
                                                        (long long)NQ * NQ, (long long)DM * NQ,
                                                        (long long)NQ * DM);
    gemm_b16<2,0><<<ggrid(MQ, DM), 256, GSMEM>>>(p_ao, Wo_l, bo_l, p_q, nullptr,
                                                 p_q, MQ, DM, DM, 0, 0, 0);

    gemm_b16<1,0><<<ggrid(MQ, DM), 256, GSMEM>>>(p_q, w_b1, b_b1, nullptr, nullptr,
                                                 p_hb, MQ, DM, DM, 0, 0, 0);
    k_box<<<MQ, 128>>>(p_hb, w_b2, b_b2, p_box);
  }

  k_logits<<<MQ, 256>>>(p_q, w_cls, b_cls, out);
  k_copyboxes<<<(MQ * 4 + 255) / 256, 256>>>(p_box, out);
}

// round 9
// speedup vs baseline: 1.6730x; 1.6730x over previous
#include <cuda_runtime.h>
#include <cuda_bf16.h>
#include <math.h>
#include <stdint.h>

// ---------------------------------------------------------------------------
// Problem constants
// ---------------------------------------------------------------------------
#define HH 64
#define WW 64
#define HWSZ 4096
#define CIN 128
#define TT 4
#define DM 256
#define NQ 300
#define NP 8
#define NLAY 6
#define BATCH 2
#define MROWS (BATCH*HWSZ)      // 8192 spatial rows
#define MQ (BATCH*NQ)           // 600 query rows
#define MS (MQ*NP)              // 4800 sample rows
#define KP1 2304                // 3*3*256

// ---------------------------------------------------------------------------
// Scratch
// ---------------------------------------------------------------------------
constexpr size_t O_WCOMB = 0;                        // 256*512
constexpr size_t O_BCOMB = O_WCOMB + 256*512;        // 256
constexpr size_t O_PY    = O_BCOMB + 256;            // 64*128
constexpr size_t O_PX    = O_PY + 64*128;            // 64*128 (contiguous after PY)
constexpr size_t O_WSMP  = O_PX + 64*128;            // 256*2304 permuted w_sm
constexpr size_t O_X     = O_WSMP + (size_t)DM*KP1;  // 8192*256
constexpr size_t O_LAT   = O_X + (size_t)MROWS*DM;   // 8192*256
constexpr size_t O_F0    = O_LAT + (size_t)MROWS*DM; // 8192*256
constexpr size_t O_Q     = O_F0 + (size_t)MROWS*DM;  // 600*256
constexpr size_t O_H1    = O_Q + MQ*DM;
constexpr size_t O_REF   = O_H1 + MQ*DM;             // 600*8*2
constexpr size_t O_FLAT  = O_REF + MQ*NP*2;          // 4800*2304
constexpr size_t O_PV    = O_FLAT + (size_t)MS*KP1;  // 4800*256
constexpr size_t O_KV    = O_PV + (size_t)MS*DM;
constexpr size_t O_QP    = O_KV + MQ*DM;
constexpr size_t O_KVT   = O_QP + MQ*DM;             // 2*256*300
constexpr size_t O_S     = O_KVT + MQ*DM;            // 2*300*300
constexpr size_t O_AO    = O_S + BATCH*NQ*NQ;
constexpr size_t O_HB    = O_AO + MQ*DM;
constexpr size_t O_BOX   = O_HB + MQ*DM;             // 600*4
constexpr size_t G_TOTAL = O_BOX + MQ*4;

__device__ float g_buf[G_TOTAL];

// ---------------------------------------------------------------------------
// BF16 split helpers
// ---------------------------------------------------------------------------
__device__ __forceinline__ void split_bf16(float x, float& hf, float& lf) {
  __nv_bfloat16 h = __float2bfloat16(x);
  hf = __bfloat162float(h);
  lf = x - hf;
}
__device__ __forceinline__ uint32_t pack_bf16(float lo_elem, float hi_elem) {
  __nv_bfloat162 t = __floats2bfloat162_rn(lo_elem, hi_elem);
  return *reinterpret_cast<uint32_t*>(&t);
}
__device__ __forceinline__ void mma_bf16(float* c, const uint32_t* a, const uint32_t* b) {
  asm volatile(
    "mma.sync.aligned.m16n8k16.row.col.f32.bf16.bf16.f32 "
    "{%0,%1,%2,%3},{%4,%5,%6,%7},{%8,%9},{%0,%1,%2,%3};"
    : "+f"(c[0]), "+f"(c[1]), "+f"(c[2]), "+f"(c[3])
    : "r"(a[0]), "r"(a[1]), "r"(a[2]), "r"(a[3]), "r"(b[0]), "r"(b[1]));
}

// ---------------------------------------------------------------------------
// 3xBF16 GEMM (Karatsuba hi/lo). Block 128x64, 8 warps of 32x32, BK=32,
// double-buffered 48KB dynamic smem, fragment-layout + XOR swizzle.
// GATHER: 0 = plain A[M,K]
//         1 = im2col of (b,64,64,256) channel-last map ([ky][kx][c] K-order)
//         2 = stem gather from feat[b][t][i][hw], k=i*4+t (coalesced over hw)
//         4 = mean over 8 point-rows of A
// EPI: 0=+bias, 1=+bias+relu, 2=+bias+res, 3=+bias+sinepos(aux)
// ---------------------------------------------------------------------------
template<int EPI, int GATHER>
__global__ __launch_bounds__(256, 2)
void gemm_b16(const float* __restrict__ A, const float* __restrict__ Bw,
              const float* __restrict__ bias, const float* __restrict__ res,
              const float* __restrict__ aux, float* __restrict__ C,
              int M, int N, int K,
              long long sA, long long sB, long long sC) {
  const int BM = 128, BN = 64, BK = 32;
  extern __shared__ uint32_t smem[];
  uint32_t* SAb = smem;            // 2 x 4096 words
  uint32_t* SBb = smem + 8192;     // 2 x 2048 words

  A  += blockIdx.z * sA;
  Bw += blockIdx.z * sB;
  C  += blockIdx.z * sC;

  int tid = threadIdx.x;
  int bm = blockIdx.y * BM, bn = blockIdx.x * BN;
  int lane = tid & 31, warp = tid >> 5;
  int wm = (warp >> 1) * 32, wn = (warp & 1) * 32;
  int gid = lane >> 2, tig = lane & 3;
  int xr = (lane >> 2) & 7;

  float acc[2][4][4] = {};
  int Kpad = (K + BK - 1) / BK * BK;

  int am4[4], ak4[4], bn2[2], bk2[2];
  #pragma unroll
  for (int l = 0; l < 4; ++l) {
    int li = tid + l * 256;
    am4[l] = li >> 3;
    ak4[l] = (li & 7) * 4;
  }
  #pragma unroll
  for (int l = 0; l < 2; ++l) {
    int li = tid + l * 256;
    bn2[l] = li >> 3;
    bk2[l] = (li & 7) * 4;
  }
  // GATHER==2 fill mapping: thread -> (m2, khalf), 16 scalar loads
  int m2 = tid & 127, khalf = tid >> 7;

  float4 pa[4], pb[2];
  float pa2[16];

  auto loadA = [&](int k0, int l) -> float4 {
    float4 v = make_float4(0.f, 0.f, 0.f, 0.f);
    int gm = bm + am4[l], gk = k0 + ak4[l];
    if (GATHER == 1) {
      if (gm < M && gk < K) {
        int ky = gk / 768, rem = gk - ky * 768;
        int kx = rem >> 8, c = rem & 255;
        int b = gm >> 12, hw = gm & 4095, h = hw >> 6, w = hw & 63;
        int hh = h + ky - 1, ww = w + kx - 1;
        if (hh >= 0 && hh < 64 && ww >= 0 && ww < 64)
          v = *reinterpret_cast<const float4*>(A + ((size_t)(b << 12) + (hh << 6) + ww) * 256 + c);
      }
    } else if (GATHER == 4) {
      if (gm < M) {
        const float* base = A + ((size_t)gm * 8) * DM + gk;
        float4 s = make_float4(0.f, 0.f, 0.f, 0.f);
        #pragma unroll
        for (int p = 0; p < 8; ++p) {
          float4 t = *reinterpret_cast<const float4*>(base + (size_t)p * DM);
          s.x += t.x; s.y += t.y; s.z += t.z; s.w += t.w;
        }
        v = make_float4(s.x * 0.125f, s.y * 0.125f, s.z * 0.125f, s.w * 0.125f);
      }
    } else {
      if (gm < M) {
        if (gk + 3 < K) v = *reinterpret_cast<const float4*>(A + (size_t)gm * K + gk);
        else {
          float t[4] = {0.f, 0.f, 0.f, 0.f};
          #pragma unroll
          for (int e = 0; e < 4; ++e) if (gk + e < K) t[e] = A[(size_t)gm * K + gk + e];
          v = make_float4(t[0], t[1], t[2], t[3]);
        }
      }
    }
    return v;
  };
  auto loadB = [&](int k0, int l) -> float4 {
    float4 v = make_float4(0.f, 0.f, 0.f, 0.f);
    int gn = bn + bn2[l], gk = k0 + bk2[l];
    if (gn < N) {
      if (gk + 3 < K) v = *reinterpret_cast<const float4*>(Bw + (size_t)gn * K + gk);
      else {
        float t[4] = {0.f, 0.f, 0.f, 0.f};
        #pragma unroll
        for (int e = 0; e < 4; ++e) if (gk + e < K) t[e] = Bw[(size_t)gn * K + gk + e];
        v = make_float4(t[0], t[1], t[2], t[3]);
      }
    }
    return v;
  };
  auto prefetch = [&](int k0) {
    if (GATHER == 2) {
      int gm = bm + m2;
      int b = gm >> 12, hw = gm & 4095;
      #pragma unroll
      for (int j = 0; j < 16; ++j) {
        int k = k0 + khalf * 16 + j;
        int i = k >> 2, t = k & 3;
        pa2[j] = A[(size_t)(((b << 2) + t) * CIN + i) * HWSZ + hw];
      }
    } else {
      #pragma unroll
      for (int l = 0; l < 4; ++l) pa[l] = loadA(k0, l);
    }
    #pragma unroll
    for (int l = 0; l < 2; ++l) pb[l] = loadB(k0, l);
  };

  auto storeTiles = [&](int buf) {
    uint32_t* SA = SAb + buf * 4096;
    uint32_t* SB = SBb + buf * 2048;
    if (GATHER == 2) {
      int tm = m2 >> 4, rr = m2 & 15;
      #pragma unroll
      for (int j = 0; j < 8; ++j) {
        int lw = (rr & 7) * 4 + (j & 3);
        int reg = (rr >> 3) | ((j >> 2) << 1);
        float h0, l0, h1, l1;
        split_bf16(pa2[2 * j], h0, l0);
        split_bf16(pa2[2 * j + 1], h1, l1);
        int s0 = (((tm * 2 + khalf) * 32 + lw) * 2) ^ ((lw >> 2) & 7);
        SA[s0 * 4 + reg]       = pack_bf16(h0, h1);
        SA[(s0 ^ 1) * 4 + reg] = pack_bf16(l0, l1);
      }
    } else {
      #pragma unroll
      for (int l = 0; l < 4; ++l) {
        float v[4] = {pa[l].x, pa[l].y, pa[l].z, pa[l].w};
        int tm = am4[l] >> 4, rr = am4[l] & 15;
        int tk = ak4[l] >> 4, k16b = ak4[l] & 15;
        #pragma unroll
        for (int e = 0; e < 2; ++e) {
          int k16p = k16b + 2 * e;
          int lw = (rr & 7) * 4 + ((k16p >> 1) & 3);
          int reg = (rr >> 3) | ((k16p >> 3) << 1);
          float h0, l0, h1, l1;
          split_bf16(v[2 * e], h0, l0);
          split_bf16(v[2 * e + 1], h1, l1);
          int s0 = (((tm * 2 + tk) * 32 + lw) * 2) ^ ((lw >> 2) & 7);
          SA[s0 * 4 + reg]       = pack_bf16(h0, h1);
          SA[(s0 ^ 1) * 4 + reg] = pack_bf16(l0, l1);
        }
      }
    }
    #pragma unroll
    for (int l = 0; l < 2; ++l) {
      float v[4] = {pb[l].x, pb[l].y, pb[l].z, pb[l].w};
      int ntile = bn2[l] >> 3, gidn = bn2[l] & 7;
      int np = ntile >> 1, nodd = ntile & 1;
      int tk = bk2[l] >> 4, k16b = bk2[l] & 15;
      #pragma unroll
      for (int e = 0; e < 2; ++e) {
        int k16p = k16b + 2 * e;
        int lw = gidn * 4 + ((k16p >> 1) & 3);
        int reg = k16p >> 3;
        int word = nodd * 2 + reg;
        float h0, l0, h1, l1;
        split_bf16(v[2 * e], h0, l0);
        split_bf16(v[2 * e + 1], h1, l1);
        int s0 = (((np * 2 + tk) * 32 + lw) * 2) ^ ((lw >> 2) & 7);
        SB[s0 * 4 + word]       = pack_bf16(h0, h1);
        SB[(s0 ^ 1) * 4 + word] = pack_bf16(l0, l1);
      }
    }
  };

  prefetch(0);
  storeTiles(0);
  if (BK < Kpad) prefetch(BK);
  __syncthreads();

  int cur = 0;
  for (int k0 = 0; k0 < Kpad; k0 += BK) {
    if (k0 + BK < Kpad) {
      storeTiles(cur ^ 1);
      if (k0 + 2 * BK < Kpad) prefetch(k0 + 2 * BK);
    }
    const uint32_t* SA = SAb + cur * 4096;
    const uint32_t* SB = SBb + cur * 2048;
    #pragma unroll
    for (int tk = 0; tk < 2; ++tk) {
      uint32_t Ahf[2][4], Alf[2][4];
      #pragma unroll
      for (int i = 0; i < 2; ++i) {
        int tm = (wm >> 4) + i;
        int s0 = (((tm * 2 + tk) * 32 + lane) * 2) ^ xr;
        *reinterpret_cast<uint4*>(Ahf[i]) = *reinterpret_cast<const uint4*>(&SA[s0 * 4]);
        *reinterpret_cast<uint4*>(Alf[i]) = *reinterpret_cast<const uint4*>(&SA[(s0 ^ 1) * 4]);
      }
      uint32_t Bhf[2][4], Blf[2][4];
      #pragma unroll
      for (int jp = 0; jp < 2; ++jp) {
        int np = (wn >> 4) + jp;
        int s0 = (((np * 2 + tk) * 32 + lane) * 2) ^ xr;
        *reinterpret_cast<uint4*>(Bhf[jp]) = *reinterpret_cast<const uint4*>(&SB[s0 * 4]);
        *reinterpret_cast<uint4*>(Blf[jp]) = *reinterpret_cast<const uint4*>(&SB[(s0 ^ 1) * 4]);
      }
      #pragma unroll
      for (int i = 0; i < 2; ++i)
        #pragma unroll
        for (int jp = 0; jp < 2; ++jp)
          #pragma unroll
          for (int nodd = 0; nodd < 2; ++nodd) {
            int j = jp * 2 + nodd;
            uint32_t bh[2] = {Bhf[jp][nodd * 2], Bhf[jp][nodd * 2 + 1]};
            uint32_t bl[2] = {Blf[jp][nodd * 2], Blf[jp][nodd * 2 + 1]};
            mma_bf16(acc[i][j], Ahf[i], bh);
            mma_bf16(acc[i][j], Ahf[i], bl);
            mma_bf16(acc[i][j], Alf[i], bh);
          }
    }
    __syncthreads();
    cur ^= 1;
  }

  #pragma unroll
  for (int i = 0; i < 2; ++i) {
    #pragma unroll
    for (int j = 0; j < 4; ++j) {
      int c0 = bn + wn + 8 * j + 2 * tig;
      #pragma unroll
      for (int half = 0; half < 2; ++half) {
        int gm = bm + wm + 16 * i + gid + 8 * half;
        if (gm >= M) continue;
        #pragma unroll
        for (int e = 0; e < 2; ++e) {
          int gn = c0 + e;
          if (gn >= N) continue;
          float v = acc[i][j][half * 2 + e] + (bias ? bias[gn] : 0.f);
          if (EPI == 1) v = fmaxf(v, 0.f);
          if (EPI == 2) v += res[(size_t)gm * N + gn];
          if (EPI == 3) {
            int hw = gm & 4095, h = hw >> 6, w = hw & 63;
            v += (gn < 128) ? aux[h * 128 + gn] : aux[8192 + w * 128 + (gn - 128)];
          }
          C[(size_t)gm * N + gn] = v;
        }
      }
    }
  }
}

// ---------------------------------------------------------------------------
// Permute w_sm [o][c][ky][kx] -> [o][ky][kx][c]
// ---------------------------------------------------------------------------
__global__ __launch_bounds__(256)
void k_wsmperm(const float* __restrict__ w_sm, float* __restrict__ out) {
  int idx = blockIdx.x * 256 + threadIdx.x;
  if (idx >= DM * KP1) return;
  int o = idx / KP1, r = idx - o * KP1;
  int ky = r / 768, rem = r - ky * 768;
  int kx = rem >> 8, c = rem & 255;
  out[idx] = w_sm[(size_t)o * KP1 + c * 9 + ky * 3 + kx];
}

// ---------------------------------------------------------------------------
// Stem weight combine
// ---------------------------------------------------------------------------
__global__ __launch_bounds__(256)
void k_wcomb(const float* __restrict__ w_tf, const float* __restrict__ w_in,
             const float* __restrict__ b_tf, const float* __restrict__ b_in,
             float* __restrict__ wcomb, float* __restrict__ bcomb) {
  int idx = blockIdx.x * 256 + threadIdx.x;
  if (idx < 256 * 512) {
    int dm = idx >> 9, k = idx & 511, i = k >> 2, t = k & 3;
    float s = 0.f;
    for (int c = 0; c < CIN; ++c) {
      const float* wt = w_tf + (c * CIN + i) * 3;
      float we = wt[1];
      if (t != 3) we += wt[0];
      if (t != 0) we += wt[2];
      s += w_in[dm * CIN + c] * we;
    }
    wcomb[idx] = 0.25f * s;
  }
  if (idx < 256) {
    float s = b_in[idx];
    for (int c = 0; c < CIN; ++c) s += w_in[idx * CIN + c] * b_tf[c];
    bcomb[idx] = s;
  }
}

__global__ __launch_bounds__(256)
void k_pos(float* __restrict__ py, float* __restrict__ px) {
  int idx = blockIdx.x * 256 + threadIdx.x;
  if (idx >= 2 * 64 * 128) return;
  int half = idx / (64 * 128);
  int r = idx - half * (64 * 128);
  int hw = r >> 7, c = r & 127;
  float dim_t = powf(10000.f, 2.f * (float)(c >> 2) / 64.f);
  float v = (float)(hw + 1) / (64.f + 1e-6f) * 2.f * 3.14159265358979323846f;
  float a = v / dim_t;
  float o = (c & 1) ? cosf(a) : sinf(a);
  if (half) px[r] = o; else py[r] = o;
}

__global__ __launch_bounds__(256)
void k_qinit(const float* __restrict__ q_embed, const float* __restrict__ q_pos,
             const float* __restrict__ boxes0, float* __restrict__ queries,
             float* __restrict__ boxes) {
  int m = blockIdx.x;
  int q = m % NQ;
  int d = threadIdx.x;
  queries[m * DM + d] = q_embed[q * DM + d] + q_pos[q * DM + d];
  if (d < 4) boxes[m * 4 + d] = boxes0[m * 4 + d];
}

__global__ __launch_bounds__(256)
void k_refpts(const float* __restrict__ h1, const float* __restrict__ boxes,
              const float* __restrict__ w_r2, const float* __restrict__ b_r2,
              float* __restrict__ ref) {
  int m = blockIdx.x;
  int g = threadIdx.x >> 4;
  int lane16 = threadIdx.x & 15;
  float s = 0.f;
  for (int d = lane16; d < DM; d += 16)
    s += h1[m * DM + d] * w_r2[g * DM + d];
  #pragma unroll
  for (int off = 8; off > 0; off >>= 1)
    s += __shfl_down_sync(0xffffffffu, s, off, 16);
  __shared__ float ro_s[16];
  if (lane16 == 0) ro_s[g] = tanhf(s + b_r2[g]) * 0.5f;
  __syncthreads();
  if (threadIdx.x < 16) {
    int p = threadIdx.x >> 1, j = threadIdx.x & 1;
    float v = boxes[m * 4 + j] + ro_s[p * 2 + j];
    ref[(m * NP + p) * 2 + j] = fminf(fmaxf(v, 0.f), 1.f);
  }
}

__global__ __launch_bounds__(256)
void k_sample(const float* __restrict__ f0, const float* __restrict__ ref,
              float* __restrict__ flat) {
  int blk = blockIdx.x;
  int kk = blk % 9;
  int rest = blk / 9;
  int p = rest & 7, m = rest >> 3;
  int b = (m >= NQ) ? 1 : 0;
  float rx = ref[(m * NP + p) * 2 + 0];
  float ry = ref[(m * NP + p) * 2 + 1];
  float oy = (float)(kk / 3 - 1), ox = (float)(kk % 3 - 1);
  float x = fminf(fmaxf((rx + ox * (1.f / 64.f)) * 63.f, 0.f), 63.f);
  float y = fminf(fmaxf((ry + oy * (1.f / 64.f)) * 63.f, 0.f), 63.f);
  float x0 = floorf(x), y0 = floorf(y);
  float wx = x - x0, wy = y - y0;
  int x0i = (int)x0, y0i = (int)y0;
  int x1i = min(x0i + 1, 63), y1i = min(y0i + 1, 63);
  int c = threadIdx.x;
  const float* f = f0 + (size_t)b * HWSZ * DM;
  float v00 = f[((y0i << 6) + x0i) * DM + c];
  float v01 = f[((y0i << 6) + x1i) * DM + c];
  float v10 = f[((y1i << 6) + x0i) * DM + c];
  float v11 = f[((y1i << 6) + x1i) * DM + c];
  float v = v00 * (1.f - wx) * (1.f - wy) + v01 * wx * (1.f - wy)
          + v10 * (1.f - wx) * wy + v11 * wx * wy;
  flat[(size_t)rest * KP1 + kk * DM + c] = v;
}

__global__ __launch_bounds__(256)
void k_kvT(const float* __restrict__ kv, float* __restrict__ kvT) {
  int m = blockIdx.x;
  int b = (m >= NQ) ? 1 : 0;
  int k = m - b * NQ;
  int d = threadIdx.x;
  kvT[((size_t)b * DM + d) * NQ + k] = kv[(size_t)m * DM + d];
}

__global__ __launch_bounds__(512)
void k_softmax(float* __restrict__ S) {
  int m = blockIdx.x;
  int b = (m >= NQ) ? 1 : 0;
  float* row = S + (size_t)b * NQ * NQ + (size_t)(m - b * NQ) * NQ;
  int t = threadIdx.x;
  __shared__ float red[512];
  float v = (t < NQ) ? row[t] * 0.0625f : -1e30f;
  red[t] = v; __syncthreads();
  for (int s = 256; s > 0; s >>= 1) { if (t < s) red[t] = fmaxf(red[t], red[t + s]); __syncthreads(); }
  float mx = red[0]; __syncthreads();
  float e = (t < NQ) ? expf(v - mx) : 0.f;
  red[t] = e; __syncthreads();
  for (int s = 256; s > 0; s >>= 1) { if (t < s) red[t] += red[t + s]; __syncthreads(); }
  float inv = 1.f / red[0];
  if (t < NQ) row[t] = e * inv;
}

__global__ __launch_bounds__(128)
void k_box(const float* __restrict__ hb, const float* __restrict__ w_b2,
           const float* __restrict__ b_b2, float* __restrict__ boxes) {
  int m = blockIdx.x;
  int wj = threadIdx.x >> 5, lane = threadIdx.x & 31;
  float s = 0.f;
  for (int d = lane; d < DM; d += 32) s += hb[m * DM + d] * w_b2[wj * DM + d];
  #pragma unroll
  for (int off = 16; off > 0; off >>= 1) s += __shfl_down_sync(0xffffffffu, s, off);
  if (lane == 0) {
    float delta = 1.f / (1.f + expf(-(s + b_b2[wj])));
    float nb = boxes[m * 4 + wj] + 0.1f * tanhf(delta - 0.5f);
    boxes[m * 4 + wj] = fminf(fmaxf(nb, 0.f), 1.f);
  }
}

__global__ __launch_bounds__(256)
void k_logits(const float* __restrict__ queries, const float* __restrict__ w_cls,
              const float* __restrict__ b_cls, float* __restrict__ out) {
  int m = blockIdx.x, t = threadIdx.x;
  __shared__ float red[256];
  red[t] = queries[m * DM + t] * w_cls[t];
  __syncthreads();
  for (int s = 128; s > 0; s >>= 1) { if (t < s) red[t] += red[t + s]; __syncthreads(); }
  if (t == 0) out[m] = red[0] + b_cls[0];
}

__global__ __launch_bounds__(256)
void k_copyboxes(const float* __restrict__ boxes, float* __restrict__ out) {
  int i = blockIdx.x * 256 + threadIdx.x;
  if (i < MQ * 4) out[MQ + i] = boxes[i];
}

// ---------------------------------------------------------------------------
static inline dim3 ggrid(int M, int N, int Z = 1) {
  return dim3((N + 63) / 64, (M + 127) / 128, Z);
}
#define GSMEM 49152

extern "C" void kernel_launch(void* const* d_in, const int* in_sizes, int n_in,
                              void* d_out, int out_size) {
  const float* feat   = (const float*)d_in[0];
  const float* boxes0 = (const float*)d_in[1];
  const float* w_tf   = (const float*)d_in[2];
  const float* b_tf   = (const float*)d_in[3];
  const float* w_in   = (const float*)d_in[4];
  const float* b_in   = (const float*)d_in[5];
  const float* w_lat  = (const float*)d_in[6];
  const float* b_lat  = (const float*)d_in[7];
  const float* w_sm   = (const float*)d_in[8];
  const float* b_sm   = (const float*)d_in[9];
  const float* q_embed= (const float*)d_in[10];
  const float* q_pos  = (const float*)d_in[11];
  const float* Wq     = (const float*)d_in[12];
  const float* bq     = (const float*)d_in[13];
  const float* Wo     = (const float*)d_in[14];
  const float* bo     = (const float*)d_in[15];
  const float* Wp1    = (const float*)d_in[16];
  const float* bp1    = (const float*)d_in[17];
  const float* Wp2    = (const float*)d_in[18];
  const float* bp2    = (const float*)d_in[19];
  const float* w_r1   = (const float*)d_in[20];
  const float* b_r1   = (const float*)d_in[21];
  const float* w_r2   = (const float*)d_in[22];
  const float* b_r2   = (const float*)d_in[23];
  const float* w_b1   = (const float*)d_in[24];
  const float* b_b1   = (const float*)d_in[25];
  const float* w_b2   = (const float*)d_in[26];
  const float* b_b2   = (const float*)d_in[27];
  const float* w_cls  = (const float*)d_in[28];
  const float* b_cls  = (const float*)d_in[29];
  float* out = (float*)d_out;

  static bool attr_done = false;
  if (!attr_done) {
    cudaFuncSetAttribute(gemm_b16<0,0>, cudaFuncAttributeMaxDynamicSharedMemorySize, GSMEM);
    cudaFuncSetAttribute(gemm_b16<1,0>, cudaFuncAttributeMaxDynamicSharedMemorySize, GSMEM);
    cudaFuncSetAttribute(gemm_b16<2,0>, cudaFuncAttributeMaxDynamicSharedMemorySize, GSMEM);
    cudaFuncSetAttribute(gemm_b16<0,1>, cudaFuncAttributeMaxDynamicSharedMemorySize, GSMEM);
    cudaFuncSetAttribute(gemm_b16<3,2>, cudaFuncAttributeMaxDynamicSharedMemorySize, GSMEM);
    cudaFuncSetAttribute(gemm_b16<0,4>, cudaFuncAttributeMaxDynamicSharedMemorySize, GSMEM);
    attr_done = true;
  }

  float* base = nullptr;
  cudaGetSymbolAddress((void**)&base, g_buf);
  float* p_wcomb = base + O_WCOMB;
  float* p_bcomb = base + O_BCOMB;
  float* p_py    = base + O_PY;     // px contiguous at +8192
  float* p_px    = base + O_PX;
  float* p_wsmp  = base + O_WSMP;
  float* p_x     = base + O_X;
  float* p_lat   = base + O_LAT;
  float* p_f0    = base + O_F0;
  float* p_q     = base + O_Q;
  float* p_h1    = base + O_H1;
  float* p_ref   = base + O_REF;
  float* p_flat  = base + O_FLAT;
  float* p_pv    = base + O_PV;
  float* p_kv    = base + O_KV;
  float* p_qp    = base + O_QP;
  float* p_kvT   = base + O_KVT;
  float* p_S     = base + O_S;
  float* p_ao    = base + O_AO;
  float* p_hb    = base + O_HB;
  float* p_box   = base + O_BOX;

  // ---- prologue: weights + pos tables ----
  k_wcomb<<<(256 * 512 + 255) / 256, 256>>>(w_tf, w_in, b_tf, b_in, p_wcomb, p_bcomb);
  k_pos<<<(2 * 64 * 128 + 255) / 256, 256>>>(p_py, p_px);
  k_wsmperm<<<(DM * KP1 + 255) / 256, 256>>>(w_sm, p_wsmp);

  // ---- stem: fused conv3d+mean_T+in-proj GEMM on tensor cores, +pos epi ----
  gemm_b16<3,2><<<ggrid(MROWS, DM), 256, GSMEM>>>(feat, p_wcomb, p_bcomb, nullptr, p_py,
                                                  p_x, MROWS, DM, 512, 0, 0, 0);

  // ---- scale-1 feature (scales 2,4 dead in reference) ----
  gemm_b16<0,0><<<ggrid(MROWS, DM), 256, GSMEM>>>(p_x, w_lat, b_lat, nullptr, nullptr,
                                                  p_lat, MROWS, DM, DM, 0, 0, 0);
  gemm_b16<0,1><<<ggrid(MROWS, DM), 256, GSMEM>>>(p_lat, p_wsmp, b_sm, nullptr, nullptr,
                                                  p_f0, MROWS, DM, KP1, 0, 0, 0);

  // ---- decoder init ----
  k_qinit<<<MQ, 256>>>(q_embed, q_pos, boxes0, p_q, p_box);

  for (int l = 0; l < NLAY; ++l) {
    const float* Wq_l  = Wq  + (size_t)l * DM * DM;
    const float* bq_l  = bq  + (size_t)l * DM;
    const float* Wo_l  = Wo  + (size_t)l * DM * DM;
    const float* bo_l  = bo  + (size_t)l * DM;
    const float* Wp1_l = Wp1 + (size_t)l * DM * KP1;
    const float* bp1_l = bp1 + (size_t)l * DM;
    const float* Wp2_l = Wp2 + (size_t)l * DM * DM;
    const float* bp2_l = bp2 + (size_t)l * DM;

    gemm_b16<1,0><<<ggrid(MQ, DM), 256, GSMEM>>>(p_q, w_r1, b_r1, nullptr, nullptr,
                                                 p_h1, MQ, DM, DM, 0, 0, 0);
    k_refpts<<<MQ, 256>>>(p_h1, p_box, w_r2, b_r2, p_ref);

    // explicit bilinear sampling into flat (R7 path — fastest measured)
    k_sample<<<MQ * NP * 9, 256>>>(p_f0, p_ref, p_flat);

    gemm_b16<1,0><<<ggrid(MS, DM), 256, GSMEM>>>(p_flat, Wp1_l, bp1_l, nullptr, nullptr,
                                                 p_pv, MS, DM, KP1, 0, 0, 0);
    // Wp2 with fused mean-over-points A-loader
    gemm_b16<0,4><<<ggrid(MQ, DM), 256, GSMEM>>>(p_pv, Wp2_l, bp2_l, nullptr, nullptr,
                                                 p_kv, MQ, DM, DM, 0, 0, 0);

    gemm_b16<0,0><<<ggrid(MQ, DM), 256, GSMEM>>>(p_q, Wq_l, bq_l, nullptr, nullptr,
                                                 p_qp, MQ, DM, DM, 0, 0, 0);
    k_kvT<<<MQ, 256>>>(p_kv, p_kvT);
    gemm_b16<0,0><<<ggrid(NQ, NQ, BATCH), 256, GSMEM>>>(p_qp, p_kv, nullptr, nullptr, nullptr, p_S,
                                                        NQ, NQ, DM,
                                                        (long long)NQ * DM, (long long)NQ * DM,
                                                        (long long)NQ * NQ);
    k_softmax<<<MQ, 512>>>(p_S);
    gemm_b16<0,0><<<ggrid(NQ, DM, BATCH), 256, GSMEM>>>(p_S, p_kvT, nullptr, nullptr, nullptr, p_ao,
                                                        NQ, DM, NQ,
                                                        (long long)NQ * NQ, (long long)DM * NQ,
                                                        (long long)NQ * DM);
    gemm_b16<2,0><<<ggrid(MQ, DM), 256, GSMEM>>>(p_ao, Wo_l, bo_l, p_q, nullptr,
                                                 p_q, MQ, DM, DM, 0, 0, 0);

    gemm_b16<1,0><<<ggrid(MQ, DM), 256, GSMEM>>>(p_q, w_b1, b_b1, nullptr, nullptr,
                                                 p_hb, MQ, DM, DM, 0, 0, 0);
    k_box<<<MQ, 128>>>(p_hb, w_b2, b_b2, p_box);
  }

  k_logits<<<MQ, 256>>>(p_q, w_cls, b_cls, out);
  k_copyboxes<<<(MQ * 4 + 255) / 256, 256>>>(p_box, out);
}

// round 11
// speedup vs baseline: 1.7790x; 1.0633x over previous
#include <cuda_runtime.h>
#include <cuda_bf16.h>
#include <math.h>
#include <stdint.h>

// ---------------------------------------------------------------------------
// Problem constants
// ---------------------------------------------------------------------------
#define HH 64
#define WW 64
#define HWSZ 4096
#define CIN 128
#define TT 4
#define DM 256
#define NQ 300
#define NP 8
#define NLAY 6
#define BATCH 2
#define MROWS (BATCH*HWSZ)      // 8192 spatial rows
#define MQ (BATCH*NQ)           // 600 query rows
#define MS (MQ*NP)              // 4800 sample rows
#define KP1 2304                // 3*3*256

// ---------------------------------------------------------------------------
// Scratch
// ---------------------------------------------------------------------------
constexpr size_t O_WCOMB = 0;                         // 256*512
constexpr size_t O_BCOMB = O_WCOMB + 256*512;         // 256
constexpr size_t O_PY    = O_BCOMB + 256;             // 64*128
constexpr size_t O_PX    = O_PY + 64*128;             // 64*128 (contiguous)
constexpr size_t O_WSMP  = O_PX + 64*128;             // 256*2304
constexpr size_t O_WCAT  = O_WSMP + (size_t)DM*KP1;   // 6*512*256
constexpr size_t O_BCAT  = O_WCAT + (size_t)NLAY*512*256; // 6*512
constexpr size_t O_X     = O_BCAT + NLAY*512;         // 8192*256
constexpr size_t O_LAT   = O_X + (size_t)MROWS*DM;    // 8192*256
constexpr size_t O_F0    = O_LAT + (size_t)MROWS*DM;  // 8192*256
constexpr size_t O_Q     = O_F0 + (size_t)MROWS*DM;   // 600*256
constexpr size_t O_H1QP  = O_Q + MQ*DM;               // 600*512
constexpr size_t O_FLAT  = O_H1QP + MQ*512;           // 4800*2304
constexpr size_t O_PV    = O_FLAT + (size_t)MS*KP1;   // 4800*256
constexpr size_t O_KV    = O_PV + (size_t)MS*DM;
constexpr size_t O_KVT   = O_KV + MQ*DM;              // 2*256*300
constexpr size_t O_S     = O_KVT + MQ*DM;             // 2*300*300
constexpr size_t O_AO    = O_S + BATCH*NQ*NQ;
constexpr size_t O_HB    = O_AO + MQ*DM;
constexpr size_t O_BOX   = O_HB + MQ*DM;              // 600*4
constexpr size_t G_TOTAL = O_BOX + MQ*4;

__device__ float g_buf[G_TOTAL];

// ---------------------------------------------------------------------------
// BF16 split helpers
// ---------------------------------------------------------------------------
__device__ __forceinline__ void split_bf16(float x, float& hf, float& lf) {
  __nv_bfloat16 h = __float2bfloat16(x);
  hf = __bfloat162float(h);
  lf = x - hf;
}
__device__ __forceinline__ uint32_t pack_bf16(float lo_elem, float hi_elem) {
  __nv_bfloat162 t = __floats2bfloat162_rn(lo_elem, hi_elem);
  return *reinterpret_cast<uint32_t*>(&t);
}
__device__ __forceinline__ void mma_bf16(float* c, const uint32_t* a, const uint32_t* b) {
  asm volatile(
    "mma.sync.aligned.m16n8k16.row.col.f32.bf16.bf16.f32 "
    "{%0,%1,%2,%3},{%4,%5,%6,%7},{%8,%9},{%0,%1,%2,%3};"
    : "+f"(c[0]), "+f"(c[1]), "+f"(c[2]), "+f"(c[3])
    : "r"(a[0]), "r"(a[1]), "r"(a[2]), "r"(a[3]), "r"(b[0]), "r"(b[1]));
}

// ---------------------------------------------------------------------------
// 3xBF16 GEMM (Karatsuba hi/lo). Block 128x64, 8 warps of 32x32, BK=32,
// double-buffered 48KB dynamic smem, fragment-layout + XOR swizzle.
// GATHER: 0 plain A[M,lda]; 1 im2col; 2 stem gather; 4 mean over 8 rows
// EPI: 0=+bias, 1=+bias+relu, 2=+bias+res, 3=+bias+sinepos(aux),
//      5=+bias,relu on gn<256 only, 6=+bias, dual write C and kvT(res)
// ---------------------------------------------------------------------------
template<int EPI, int GATHER>
__global__ __launch_bounds__(256, 2)
void gemm_b16(const float* __restrict__ A, const float* __restrict__ Bw,
              const float* __restrict__ bias, const float* __restrict__ res,
              const float* __restrict__ aux, float* __restrict__ C,
              int M, int N, int K, int lda,
              long long sA, long long sB, long long sC) {
  const int BM = 128, BN = 64, BK = 32;
  extern __shared__ uint32_t smem[];
  uint32_t* SAb = smem;
  uint32_t* SBb = smem + 8192;

  A  += blockIdx.z * sA;
  Bw += blockIdx.z * sB;
  C  += blockIdx.z * sC;

  int tid = threadIdx.x;
  int bm = blockIdx.y * BM, bn = blockIdx.x * BN;
  int lane = tid & 31, warp = tid >> 5;
  int wm = (warp >> 1) * 32, wn = (warp & 1) * 32;
  int gid = lane >> 2, tig = lane & 3;
  int xr = (lane >> 2) & 7;

  float acc[2][4][4] = {};
  int Kpad = (K + BK - 1) / BK * BK;

  int am4[4], ak4[4], bn2[2], bk2[2];
  #pragma unroll
  for (int l = 0; l < 4; ++l) {
    int li = tid + l * 256;
    am4[l] = li >> 3;
    ak4[l] = (li & 7) * 4;
  }
  #pragma unroll
  for (int l = 0; l < 2; ++l) {
    int li = tid + l * 256;
    bn2[l] = li >> 3;
    bk2[l] = (li & 7) * 4;
  }
  int m2 = tid & 127, khalf = tid >> 7;

  float4 pa[4], pb[2];
  float pa2[16];

  auto loadA = [&](int k0, int l) -> float4 {
    float4 v = make_float4(0.f, 0.f, 0.f, 0.f);
    int gm = bm + am4[l], gk = k0 + ak4[l];
    if (GATHER == 1) {
      if (gm < M && gk < K) {
        int ky = gk / 768, rem = gk - ky * 768;
        int kx = rem >> 8, c = rem & 255;
        int b = gm >> 12, hw = gm & 4095, h = hw >> 6, w = hw & 63;
        int hh = h + ky - 1, ww = w + kx - 1;
        if (hh >= 0 && hh < 64 && ww >= 0 && ww < 64)
          v = *reinterpret_cast<const float4*>(A + ((size_t)(b << 12) + (hh << 6) + ww) * 256 + c);
      }
    } else if (GATHER == 4) {
      if (gm < M) {
        const float* base = A + ((size_t)gm * 8) * DM + gk;
        float4 s = make_float4(0.f, 0.f, 0.f, 0.f);
        #pragma unroll
        for (int p = 0; p < 8; ++p) {
          float4 t = *reinterpret_cast<const float4*>(base + (size_t)p * DM);
          s.x += t.x; s.y += t.y; s.z += t.z; s.w += t.w;
        }
        v = make_float4(s.x * 0.125f, s.y * 0.125f, s.z * 0.125f, s.w * 0.125f);
      }
    } else {
      if (gm < M) {
        if (gk + 3 < K) v = *reinterpret_cast<const float4*>(A + (size_t)gm * lda + gk);
        else {
          float t[4] = {0.f, 0.f, 0.f, 0.f};
          #pragma unroll
          for (int e = 0; e < 4; ++e) if (gk + e < K) t[e] = A[(size_t)gm * lda + gk + e];
          v = make_float4(t[0], t[1], t[2], t[3]);
        }
      }
    }
    return v;
  };
  auto loadB = [&](int k0, int l) -> float4 {
    float4 v = make_float4(0.f, 0.f, 0.f, 0.f);
    int gn = bn + bn2[l], gk = k0 + bk2[l];
    if (gn < N) {
      if (gk + 3 < K) v = *reinterpret_cast<const float4*>(Bw + (size_t)gn * K + gk);
      else {
        float t[4] = {0.f, 0.f, 0.f, 0.f};
        #pragma unroll
        for (int e = 0; e < 4; ++e) if (gk + e < K) t[e] = Bw[(size_t)gn * K + gk + e];
        v = make_float4(t[0], t[1], t[2], t[3]);
      }
    }
    return v;
  };
  auto prefetch = [&](int k0) {
    if (GATHER == 2) {
      int gm = bm + m2;
      int b = gm >> 12, hw = gm & 4095;
      #pragma unroll
      for (int j = 0; j < 16; ++j) {
        int k = k0 + khalf * 16 + j;
        int i = k >> 2, t = k & 3;
        pa2[j] = A[(size_t)(((b << 2) + t) * CIN + i) * HWSZ + hw];
      }
    } else {
      #pragma unroll
      for (int l = 0; l < 4; ++l) pa[l] = loadA(k0, l);
    }
    #pragma unroll
    for (int l = 0; l < 2; ++l) pb[l] = loadB(k0, l);
  };

  auto storeTiles = [&](int buf) {
    uint32_t* SA = SAb + buf * 4096;
    uint32_t* SB = SBb + buf * 2048;
    if (GATHER == 2) {
      int tm = m2 >> 4, rr = m2 & 15;
      #pragma unroll
      for (int j = 0; j < 8; ++j) {
        int lw = (rr & 7) * 4 + (j & 3);
        int reg = (rr >> 3) | ((j >> 2) << 1);
        float h0, l0, h1, l1;
        split_bf16(pa2[2 * j], h0, l0);
        split_bf16(pa2[2 * j + 1], h1, l1);
        int s0 = (((tm * 2 + khalf) * 32 + lw) * 2) ^ ((lw >> 2) & 7);
        SA[s0 * 4 + reg]       = pack_bf16(h0, h1);
        SA[(s0 ^ 1) * 4 + reg] = pack_bf16(l0, l1);
      }
    } else {
      #pragma unroll
      for (int l = 0; l < 4; ++l) {
        float v[4] = {pa[l].x, pa[l].y, pa[l].z, pa[l].w};
        int tm = am4[l] >> 4, rr = am4[l] & 15;
        int tk = ak4[l] >> 4, k16b = ak4[l] & 15;
        #pragma unroll
        for (int e = 0; e < 2; ++e) {
          int k16p = k16b + 2 * e;
          int lw = (rr & 7) * 4 + ((k16p >> 1) & 3);
          int reg = (rr >> 3) | ((k16p >> 3) << 1);
          float h0, l0, h1, l1;
          split_bf16(v[2 * e], h0, l0);
          split_bf16(v[2 * e + 1], h1, l1);
          int s0 = (((tm * 2 + tk) * 32 + lw) * 2) ^ ((lw >> 2) & 7);
          SA[s0 * 4 + reg]       = pack_bf16(h0, h1);
          SA[(s0 ^ 1) * 4 + reg] = pack_bf16(l0, l1);
        }
      }
    }
    #pragma unroll
    for (int l = 0; l < 2; ++l) {
      float v[4] = {pb[l].x, pb[l].y, pb[l].z, pb[l].w};
      int ntile = bn2[l] >> 3, gidn = bn2[l] & 7;
      int np = ntile >> 1, nodd = ntile & 1;
      int tk = bk2[l] >> 4, k16b = bk2[l] & 15;
      #pragma unroll
      for (int e = 0; e < 2; ++e) {
        int k16p = k16b + 2 * e;
        int lw = gidn * 4 + ((k16p >> 1) & 3);
        int reg = k16p >> 3;
        int word = nodd * 2 + reg;
        float h0, l0, h1, l1;
        split_bf16(v[2 * e], h0, l0);
        split_bf16(v[2 * e + 1], h1, l1);
        int s0 = (((np * 2 + tk) * 32 + lw) * 2) ^ ((lw >> 2) & 7);
        SB[s0 * 4 + word]       = pack_bf16(h0, h1);
        SB[(s0 ^ 1) * 4 + word] = pack_bf16(l0, l1);
      }
    }
  };

  prefetch(0);
  storeTiles(0);
  if (BK < Kpad) prefetch(BK);
  __syncthreads();

  int cur = 0;
  for (int k0 = 0; k0 < Kpad; k0 += BK) {
    if (k0 + BK < Kpad) {
      storeTiles(cur ^ 1);
      if (k0 + 2 * BK < Kpad) prefetch(k0 + 2 * BK);
    }
    const uint32_t* SA = SAb + cur * 4096;
    const uint32_t* SB = SBb + cur * 2048;
    #pragma unroll
    for (int tk = 0; tk < 2; ++tk) {
      uint32_t Ahf[2][4], Alf[2][4];
      #pragma unroll
      for (int i = 0; i < 2; ++i) {
        int tm = (wm >> 4) + i;
        int s0 = (((tm * 2 + tk) * 32 + lane) * 2) ^ xr;
        *reinterpret_cast<uint4*>(Ahf[i]) = *reinterpret_cast<const uint4*>(&SA[s0 * 4]);
        *reinterpret_cast<uint4*>(Alf[i]) = *reinterpret_cast<const uint4*>(&SA[(s0 ^ 1) * 4]);
      }
      uint32_t Bhf[2][4], Blf[2][4];
      #pragma unroll
      for (int jp = 0; jp < 2; ++jp) {
        int np = (wn >> 4) + jp;
        int s0 = (((np * 2 + tk) * 32 + lane) * 2) ^ xr;
        *reinterpret_cast<uint4*>(Bhf[jp]) = *reinterpret_cast<const uint4*>(&SB[s0 * 4]);
        *reinterpret_cast<uint4*>(Blf[jp]) = *reinterpret_cast<const uint4*>(&SB[(s0 ^ 1) * 4]);
      }
      #pragma unroll
      for (int i = 0; i < 2; ++i)
        #pragma unroll
        for (int jp = 0; jp < 2; ++jp)
          #pragma unroll
          for (int nodd = 0; nodd < 2; ++nodd) {
            int j = jp * 2 + nodd;
            uint32_t bh[2] = {Bhf[jp][nodd * 2], Bhf[jp][nodd * 2 + 1]};
            uint32_t bl[2] = {Blf[jp][nodd * 2], Blf[jp][nodd * 2 + 1]};
            mma_bf16(acc[i][j], Ahf[i], bh);
            mma_bf16(acc[i][j], Ahf[i], bl);
            mma_bf16(acc[i][j], Alf[i], bh);
          }
    }
    __syncthreads();
    cur ^= 1;
  }

  #pragma unroll
  for (int i = 0; i < 2; ++i) {
    #pragma unroll
    for (int j = 0; j < 4; ++j) {
      int c0 = bn + wn + 8 * j + 2 * tig;
      #pragma unroll
      for (int half = 0; half < 2; ++half) {
        int gm = bm + wm + 16 * i + gid + 8 * half;
        if (gm >= M) continue;
        #pragma unroll
        for (int e = 0; e < 2; ++e) {
          int gn = c0 + e;
          if (gn >= N) continue;
          float v = acc[i][j][half * 2 + e] + (bias ? bias[gn] : 0.f);
          if (EPI == 1) v = fmaxf(v, 0.f);
          if (EPI == 2) v += res[(size_t)gm * N + gn];
          if (EPI == 3) {
            int hw = gm & 4095, h = hw >> 6, w = hw & 63;
            v += (gn < 128) ? aux[h * 128 + gn] : aux[8192 + w * 128 + (gn - 128)];
          }
          if (EPI == 5) { if (gn < 256) v = fmaxf(v, 0.f); }
          if (EPI == 6) {
            int b = (gm >= NQ) ? 1 : 0;
            int kq = gm - b * NQ;
            ((float*)res)[((size_t)(b * DM + gn)) * NQ + kq] = v;
          }
          C[(size_t)gm * N + gn] = v;
        }
      }
    }
  }
}

// ---------------------------------------------------------------------------
// Prologue mega-kernel: sections by blockIdx.x
//  [0,512)       wcomb (256*512 elems) + bcomb
//  [512,576)     sine pos tables
//  [576,2880)    w_sm permute
//  [2880,5952)   wcat: 6 layers x 512 rows of [w_r1 ; Wq_l] + bcat
//  [5952,6552)   qinit + boxes init
// ---------------------------------------------------------------------------
#define PRO_GRID 6552
__global__ __launch_bounds__(256)
void k_prologue(const float* __restrict__ w_tf, const float* __restrict__ w_in,
                const float* __restrict__ b_tf, const float* __restrict__ b_in,
                const float* __restrict__ w_sm,
                const float* __restrict__ w_r1, const float* __restrict__ b_r1,
                const float* __restrict__ Wq,  const float* __restrict__ bq,
                const float* __restrict__ q_embed, const float* __restrict__ q_pos,
                const float* __restrict__ boxes0,
                float* __restrict__ wcomb, float* __restrict__ bcomb,
                float* __restrict__ pos,   float* __restrict__ wsmp,
                float* __restrict__ wcat,  float* __restrict__ bcat,
                float* __restrict__ queries, float* __restrict__ boxes) {
  int blk = blockIdx.x, tid = threadIdx.x;
  if (blk < 512) {
    int idx = blk * 256 + tid;
    int dm = idx >> 9, k = idx & 511, i = k >> 2, t = k & 3;
    float s = 0.f;
    for (int c = 0; c < CIN; ++c) {
      const float* wt = w_tf + (c * CIN + i) * 3;
      float we = wt[1];
      if (t != 3) we += wt[0];
      if (t != 0) we += wt[2];
      s += w_in[dm * CIN + c] * we;
    }
    wcomb[idx] = 0.25f * s;
    if (idx < 256) {
      float sb = b_in[idx];
      for (int c = 0; c < CIN; ++c) sb += w_in[idx * CIN + c] * b_tf[c];
      bcomb[idx] = sb;
    }
  } else if (blk < 576) {
    int idx = (blk - 512) * 256 + tid;      // 0..16383
    int half = idx >> 13;
    int r = idx & 8191;
    int hw = r >> 7, c = r & 127;
    float dim_t = powf(10000.f, 2.f * (float)(c >> 2) / 64.f);
    float v = (float)(hw + 1) / (64.f + 1e-6f) * 2.f * 3.14159265358979323846f;
    float a = v / dim_t;
    float o = (c & 1) ? cosf(a) : sinf(a);
    pos[half * 8192 + r] = o;
  } else if (blk < 2880) {
    int idx = (blk - 576) * 256 + tid;      // DM*KP1
    int o = idx / KP1, r = idx - o * KP1;
    int ky = r / 768, rem = r - ky * 768;
    int kx = rem >> 8, c = rem & 255;
    wsmp[idx] = w_sm[(size_t)o * KP1 + c * 9 + ky * 3 + kx];
  } else if (blk < 5952) {
    int r3 = blk - 2880;                    // 0..3071
    int l = r3 >> 9, row = r3 & 511;
    const float* src = (row < 256) ? (w_r1 + (size_t)row * 256)
                                   : (Wq + (size_t)l * 65536 + (size_t)(row - 256) * 256);
    wcat[((size_t)l * 512 + row) * 256 + tid] = src[tid];
    if (tid == 0)
      bcat[l * 512 + row] = (row < 256) ? b_r1[row] : bq[l * 256 + row - 256];
  } else {
    int m = blk - 5952;                     // 0..599
    int q = m % NQ;
    queries[m * DM + tid] = q_embed[q * DM + tid] + q_pos[q * DM + tid];
    if (tid < 4) boxes[m * 4 + tid] = boxes0[m * 4 + tid];
  }
}

// ---------------------------------------------------------------------------
// Fused refpoint computation + bilinear patch sampling. grid=600, block=256.
// ---------------------------------------------------------------------------
__global__ __launch_bounds__(256)
void k_refsample(const float* __restrict__ h1qp, const float* __restrict__ boxes,
                 const float* __restrict__ w_r2, const float* __restrict__ b_r2,
                 const float* __restrict__ f0, float* __restrict__ flat) {
  int m = blockIdx.x;
  int g = threadIdx.x >> 4, lane16 = threadIdx.x & 15;
  float s = 0.f;
  for (int d = lane16; d < DM; d += 16)
    s += h1qp[m * 512 + d] * w_r2[g * DM + d];
  #pragma unroll
  for (int off = 8; off > 0; off >>= 1)
    s += __shfl_down_sync(0xffffffffu, s, off, 16);
  __shared__ float ro_s[16];
  __shared__ float ref_s[8][2];
  if (lane16 == 0) ro_s[g] = tanhf(s + b_r2[g]) * 0.5f;
  __syncthreads();
  if (threadIdx.x < 16) {
    int p = threadIdx.x >> 1, j = threadIdx.x & 1;
    float v = boxes[m * 4 + j] + ro_s[p * 2 + j];
    ref_s[p][j] = fminf(fmaxf(v, 0.f), 1.f);
  }
  __syncthreads();

  int b = (m >= NQ) ? 1 : 0;
  const float* f = f0 + (size_t)b * HWSZ * DM;
  int c = threadIdx.x;
  float* outm = flat + (size_t)m * 8 * KP1;
  #pragma unroll 1
  for (int p = 0; p < 8; ++p) {
    float rx = ref_s[p][0], ry = ref_s[p][1];
    float* outp = outm + (size_t)p * KP1;
    #pragma unroll 1
    for (int kk = 0; kk < 9; ++kk) {
      float oy = (float)(kk / 3 - 1), ox = (float)(kk % 3 - 1);
      float x = fminf(fmaxf((rx + ox * (1.f / 64.f)) * 63.f, 0.f), 63.f);
      float y = fminf(fmaxf((ry + oy * (1.f / 64.f)) * 63.f, 0.f), 63.f);
      float x0 = floorf(x), y0 = floorf(y);
      float wx = x - x0, wy = y - y0;
      int x0i = (int)x0, y0i = (int)y0;
      int x1i = min(x0i + 1, 63), y1i = min(y0i + 1, 63);
      float v00 = f[((y0i << 6) + x0i) * DM + c];
      float v01 = f[((y0i << 6) + x1i) * DM + c];
      float v10 = f[((y1i << 6) + x0i) * DM + c];
      float v11 = f[((y1i << 6) + x1i) * DM + c];
      float v = v00 * (1.f - wx) * (1.f - wy) + v01 * wx * (1.f - wy)
              + v10 * (1.f - wx) * wy + v11 * wx * wy;
      outp[kk * 256 + c] = v;
    }
  }
}

__global__ __launch_bounds__(512)
void k_softmax(float* __restrict__ S) {
  int m = blockIdx.x;
  int b = (m >= NQ) ? 1 : 0;
  float* row = S + (size_t)b * NQ * NQ + (size_t)(m - b * NQ) * NQ;
  int t = threadIdx.x;
  __shared__ float red[512];
  float v = (t < NQ) ? row[t] * 0.0625f : -1e30f;
  red[t] = v; __syncthreads();
  for (int s = 256; s > 0; s >>= 1) { if (t < s) red[t] = fmaxf(red[t], red[t + s]); __syncthreads(); }
  float mx = red[0]; __syncthreads();
  float e = (t < NQ) ? expf(v - mx) : 0.f;
  red[t] = e; __syncthreads();
  for (int s = 256; s > 0; s >>= 1) { if (t < s) red[t] += red[t + s]; __syncthreads(); }
  float inv = 1.f / red[0];
  if (t < NQ) row[t] = e * inv;
}

__global__ __launch_bounds__(128)
void k_box(const float* __restrict__ hb, const float* __restrict__ w_b2,
           const float* __restrict__ b_b2, float* __restrict__ boxes) {
  int m = blockIdx.x;
  int wj = threadIdx.x >> 5, lane = threadIdx.x & 31;
  float s = 0.f;
  for (int d = lane; d < DM; d += 32) s += hb[m * DM + d] * w_b2[wj * DM + d];
  #pragma unroll
  for (int off = 16; off > 0; off >>= 1) s += __shfl_down_sync(0xffffffffu, s, off);
  if (lane == 0) {
    float delta = 1.f / (1.f + expf(-(s + b_b2[wj])));
    float nb = boxes[m * 4 + wj] + 0.1f * tanhf(delta - 0.5f);
    boxes[m * 4 + wj] = fminf(fmaxf(nb, 0.f), 1.f);
  }
}

// Epilogue: blocks [0,600) logits; [600,610) box copy
__global__ __launch_bounds__(256)
void k_final(const float* __restrict__ queries, const float* __restrict__ w_cls,
             const float* __restrict__ b_cls, const float* __restrict__ boxes,
             float* __restrict__ out) {
  int blk = blockIdx.x, t = threadIdx.x;
  if (blk < MQ) {
    __shared__ float red[256];
    red[t] = queries[blk * DM + t] * w_cls[t];
    __syncthreads();
    for (int s = 128; s > 0; s >>= 1) { if (t < s) red[t] += red[t + s]; __syncthreads(); }
    if (t == 0) out[blk] = red[0] + b_cls[0];
  } else {
    int i = (blk - MQ) * 256 + t;
    if (i < MQ * 4) out[MQ + i] = boxes[i];
  }
}

// ---------------------------------------------------------------------------
static inline dim3 ggrid(int M, int N, int Z = 1) {
  return dim3((N + 63) / 64, (M + 127) / 128, Z);
}
#define GSMEM 49152

extern "C" void kernel_launch(void* const* d_in, const int* in_sizes, int n_in,
                              void* d_out, int out_size) {
  const float* feat   = (const float*)d_in[0];
  const float* boxes0 = (const float*)d_in[1];
  const float* w_tf   = (const float*)d_in[2];
  const float* b_tf   = (const float*)d_in[3];
  const float* w_in   = (const float*)d_in[4];
  const float* b_in   = (const float*)d_in[5];
  const float* w_lat  = (const float*)d_in[6];
  const float* b_lat  = (const float*)d_in[7];
  const float* w_sm   = (const float*)d_in[8];
  const float* b_sm   = (const float*)d_in[9];
  const float* q_embed= (const float*)d_in[10];
  const float* q_pos  = (const float*)d_in[11];
  const float* Wq     = (const float*)d_in[12];
  const float* bq     = (const float*)d_in[13];
  const float* Wo     = (const float*)d_in[14];
  const float* bo     = (const float*)d_in[15];
  const float* Wp1    = (const float*)d_in[16];
  const float* bp1    = (const float*)d_in[17];
  const float* Wp2    = (const float*)d_in[18];
  const float* bp2    = (const float*)d_in[19];
  const float* w_r1   = (const float*)d_in[20];
  const float* b_r1   = (const float*)d_in[21];
  const float* w_r2   = (const float*)d_in[22];
  const float* b_r2   = (const float*)d_in[23];
  const float* w_b1   = (const float*)d_in[24];
  const float* b_b1   = (const float*)d_in[25];
  const float* w_b2   = (const float*)d_in[26];
  const float* b_b2   = (const float*)d_in[27];
  const float* w_cls  = (const float*)d_in[28];
  const float* b_cls  = (const float*)d_in[29];
  float* out = (float*)d_out;

  static bool attr_done = false;
  if (!attr_done) {
    cudaFuncSetAttribute(gemm_b16<0,0>, cudaFuncAttributeMaxDynamicSharedMemorySize, GSMEM);
    cudaFuncSetAttribute(gemm_b16<1,0>, cudaFuncAttributeMaxDynamicSharedMemorySize, GSMEM);
    cudaFuncSetAttribute(gemm_b16<2,0>, cudaFuncAttributeMaxDynamicSharedMemorySize, GSMEM);
    cudaFuncSetAttribute(gemm_b16<0,1>, cudaFuncAttributeMaxDynamicSharedMemorySize, GSMEM);
    cudaFuncSetAttribute(gemm_b16<3,2>, cudaFuncAttributeMaxDynamicSharedMemorySize, GSMEM);
    cudaFuncSetAttribute(gemm_b16<5,0>, cudaFuncAttributeMaxDynamicSharedMemorySize, GSMEM);
    cudaFuncSetAttribute(gemm_b16<6,4>, cudaFuncAttributeMaxDynamicSharedMemorySize, GSMEM);
    attr_done = true;
  }

  float* base = nullptr;
  cudaGetSymbolAddress((void**)&base, g_buf);
  float* p_wcomb = base + O_WCOMB;
  float* p_bcomb = base + O_BCOMB;
  float* p_py    = base + O_PY;     // px contiguous at +8192
  float* p_wsmp  = base + O_WSMP;
  float* p_wcat  = base + O_WCAT;
  float* p_bcat  = base + O_BCAT;
  float* p_x     = base + O_X;
  float* p_lat   = base + O_LAT;
  float* p_f0    = base + O_F0;
  float* p_q     = base + O_Q;
  float* p_h1qp  = base + O_H1QP;
  float* p_flat  = base + O_FLAT;
  float* p_pv    = base + O_PV;
  float* p_kv    = base + O_KV;
  float* p_kvT   = base + O_KVT;
  float* p_S     = base + O_S;
  float* p_ao    = base + O_AO;
  float* p_hb    = base + O_HB;
  float* p_box   = base + O_BOX;

  // ---- single prologue launch (weights, pos, permute, wcat, qinit) ----
  k_prologue<<<PRO_GRID, 256>>>(w_tf, w_in, b_tf, b_in, w_sm,
                                w_r1, b_r1, Wq, bq, q_embed, q_pos, boxes0,
                                p_wcomb, p_bcomb, p_py, p_wsmp,
                                p_wcat, p_bcat, p_q, p_box);

  // ---- stem: fused conv3d+mean_T+in-proj GEMM, +pos epi ----
  gemm_b16<3,2><<<ggrid(MROWS, DM), 256, GSMEM>>>(feat, p_wcomb, p_bcomb, nullptr, p_py,
                                                  p_x, MROWS, DM, 512, 512, 0, 0, 0);

  // ---- scale-1 feature ----
  gemm_b16<0,0><<<ggrid(MROWS, DM), 256, GSMEM>>>(p_x, w_lat, b_lat, nullptr, nullptr,
                                                  p_lat, MROWS, DM, DM, DM, 0, 0, 0);
  gemm_b16<0,1><<<ggrid(MROWS, DM), 256, GSMEM>>>(p_lat, p_wsmp, b_sm, nullptr, nullptr,
                                                  p_f0, MROWS, DM, KP1, KP1, 0, 0, 0);

  for (int l = 0; l < NLAY; ++l) {
    const float* Wo_l  = Wo  + (size_t)l * DM * DM;
    const float* bo_l  = bo  + (size_t)l * DM;
    const float* Wp1_l = Wp1 + (size_t)l * DM * KP1;
    const float* bp1_l = bp1 + (size_t)l * DM;
    const float* Wp2_l = Wp2 + (size_t)l * DM * DM;
    const float* bp2_l = bp2 + (size_t)l * DM;

    // merged r1 + Wq GEMM: N=512 ([h1 | qp]), relu on lower half only
    gemm_b16<5,0><<<ggrid(MQ, 512), 256, GSMEM>>>(p_q, p_wcat + (size_t)l * 512 * 256,
                                                  p_bcat + (size_t)l * 512, nullptr, nullptr,
                                                  p_h1qp, MQ, 512, DM, DM, 0, 0, 0);

    // fused refpoints + bilinear patch sampling
    k_refsample<<<MQ, 256>>>(p_h1qp, p_box, w_r2, b_r2, p_f0, p_flat);

    gemm_b16<1,0><<<ggrid(MS, DM), 256, GSMEM>>>(p_flat, Wp1_l, bp1_l, nullptr, nullptr,
                                                 p_pv, MS, DM, KP1, KP1, 0, 0, 0);
    // Wp2: fused mean-over-points loader + dual write (kv and kvT)
    gemm_b16<6,4><<<ggrid(MQ, DM), 256, GSMEM>>>(p_pv, Wp2_l, bp2_l, p_kvT, nullptr,
                                                 p_kv, MQ, DM, DM, DM, 0, 0, 0);

    // attention: S = qp @ kv^T (qp strided inside h1qp)
    gemm_b16<0,0><<<ggrid(NQ, NQ, BATCH), 256, GSMEM>>>(p_h1qp + 256, p_kv, nullptr, nullptr, nullptr,
                                                        p_S, NQ, NQ, DM, 512,
                                                        (long long)NQ * 512, (long long)NQ * DM,
                                                        (long long)NQ * NQ);
    k_softmax<<<MQ, 512>>>(p_S);
    gemm_b16<0,0><<<ggrid(NQ, DM, BATCH), 256, GSMEM>>>(p_S, p_kvT, nullptr, nullptr, nullptr,
                                                        p_ao, NQ, DM, NQ, NQ,
                                                        (long long)NQ * NQ, (long long)DM * NQ,
                                                        (long long)NQ * DM);
    gemm_b16<2,0><<<ggrid(MQ, DM), 256, GSMEM>>>(p_ao, Wo_l, bo_l, p_q, nullptr,
                                                 p_q, MQ, DM, DM, DM, 0, 0, 0);

    gemm_b16<1,0><<<ggrid(MQ, DM), 256, GSMEM>>>(p_q, w_b1, b_b1, nullptr, nullptr,
                                                 p_hb, MQ, DM, DM, DM, 0, 0, 0);
    k_box<<<MQ, 128>>>(p_hb, w_b2, b_b2, p_box);
  }

  k_final<<<MQ + 10, 256>>>(p_q, w_cls, b_cls, p_box, out);
}

// round 12
// speedup vs baseline: 1.8759x; 1.0545x over previous
#include <cuda_runtime.h>
#include <cuda_bf16.h>
#include <math.h>
#include <stdint.h>

// ---------------------------------------------------------------------------
// Problem constants
// ---------------------------------------------------------------------------
#define HH 64
#define WW 64
#define HWSZ 4096
#define CIN 128
#define TT 4
#define DM 256
#define NQ 300
#define NP 8
#define NLAY 6
#define BATCH 2
#define MROWS (BATCH*HWSZ)      // 8192 spatial rows
#define MQ (BATCH*NQ)           // 600 query rows
#define MS (MQ*NP)              // 4800 sample rows
#define KP1 2304                // 3*3*256

// ---------------------------------------------------------------------------
// Scratch
// ---------------------------------------------------------------------------
constexpr size_t O_WCOMB = 0;                         // 256*512
constexpr size_t O_BCOMB = O_WCOMB + 256*512;         // 256
constexpr size_t O_PY    = O_BCOMB + 256;             // 64*128
constexpr size_t O_PX    = O_PY + 64*128;             // 64*128 (contiguous)
constexpr size_t O_WSMP  = O_PX + 64*128;             // 256*2304
constexpr size_t O_WCAT  = O_WSMP + (size_t)DM*KP1;   // 6*768*256
constexpr size_t O_BCAT  = O_WCAT + (size_t)NLAY*768*256; // 6*768
constexpr size_t O_X     = O_BCAT + NLAY*768;         // 8192*256
constexpr size_t O_LAT   = O_X + (size_t)MROWS*DM;    // 8192*256
constexpr size_t O_F0    = O_LAT + (size_t)MROWS*DM;  // 8192*256
constexpr size_t O_Q     = O_F0 + (size_t)MROWS*DM;   // 600*256
constexpr size_t O_HHQ   = O_Q + MQ*DM;               // 600*768 [hb|h1|qp]
constexpr size_t O_FLAT  = O_HHQ + (size_t)MQ*768;    // 4800*2304
constexpr size_t O_PV    = O_FLAT + (size_t)MS*KP1;   // 4800*256
constexpr size_t O_KV    = O_PV + (size_t)MS*DM;
constexpr size_t O_KVT   = O_KV + MQ*DM;              // 2*256*300
constexpr size_t O_S     = O_KVT + MQ*DM;             // 2*300*300
constexpr size_t O_AO    = O_S + BATCH*NQ*NQ;
constexpr size_t O_HB    = O_AO + MQ*DM;              // final hb 600*256
constexpr size_t O_BOX   = O_HB + MQ*DM;              // 600*4
constexpr size_t G_TOTAL = O_BOX + MQ*4;

__device__ float g_buf[G_TOTAL];

// ---------------------------------------------------------------------------
// BF16 split helpers
// ---------------------------------------------------------------------------
__device__ __forceinline__ void split_bf16(float x, float& hf, float& lf) {
  __nv_bfloat16 h = __float2bfloat16(x);
  hf = __bfloat162float(h);
  lf = x - hf;
}
__device__ __forceinline__ uint32_t pack_bf16(float lo_elem, float hi_elem) {
  __nv_bfloat162 t = __floats2bfloat162_rn(lo_elem, hi_elem);
  return *reinterpret_cast<uint32_t*>(&t);
}
__device__ __forceinline__ void mma_bf16(float* c, const uint32_t* a, const uint32_t* b) {
  asm volatile(
    "mma.sync.aligned.m16n8k16.row.col.f32.bf16.bf16.f32 "
    "{%0,%1,%2,%3},{%4,%5,%6,%7},{%8,%9},{%0,%1,%2,%3};"
    : "+f"(c[0]), "+f"(c[1]), "+f"(c[2]), "+f"(c[3])
    : "r"(a[0]), "r"(a[1]), "r"(a[2]), "r"(a[3]), "r"(b[0]), "r"(b[1]));
}

// ---------------------------------------------------------------------------
// 3xBF16 GEMM (Karatsuba hi/lo). Block 128x64, 8 warps of 32x32, BK=32,
// double-buffered 48KB dynamic smem, fragment-layout + XOR swizzle.
// GATHER: 0 plain A[M,lda]; 1 im2col (tap-hoisted); 2 stem gather; 4 mean/8
// EPI: 0=+bias, 1=+bias+relu, 2=+bias+res, 3=+bias+sinepos(aux),
//      5=+bias, relu on gn<512 only, 6=+bias, dual write C and kvT(res)
// ---------------------------------------------------------------------------
template<int EPI, int GATHER>
__global__ __launch_bounds__(256, 2)
void gemm_b16(const float* __restrict__ A, const float* __restrict__ Bw,
              const float* __restrict__ bias, const float* __restrict__ res,
              const float* __restrict__ aux, float* __restrict__ C,
              int M, int N, int K, int lda,
              long long sA, long long sB, long long sC) {
  const int BM = 128, BN = 64, BK = 32;
  extern __shared__ uint32_t smem[];
  uint32_t* SAb = smem;
  uint32_t* SBb = smem + 8192;

  A  += blockIdx.z * sA;
  Bw += blockIdx.z * sB;
  C  += blockIdx.z * sC;

  int tid = threadIdx.x;
  int bm = blockIdx.y * BM, bn = blockIdx.x * BN;
  int lane = tid & 31, warp = tid >> 5;
  int wm = (warp >> 1) * 32, wn = (warp & 1) * 32;
  int gid = lane >> 2, tig = lane & 3;
  int xr = (lane >> 2) & 7;

  float acc[2][4][4] = {};
  int Kpad = (K + BK - 1) / BK * BK;

  int am4[4], ak4[4], bn2[2], bk2[2];
  #pragma unroll
  for (int l = 0; l < 4; ++l) {
    int li = tid + l * 256;
    am4[l] = li >> 3;
    ak4[l] = (li & 7) * 4;
  }
  #pragma unroll
  for (int l = 0; l < 2; ++l) {
    int li = tid + l * 256;
    bn2[l] = li >> 3;
    bk2[l] = (li & 7) * 4;
  }
  int m2 = tid & 127, khalf = tid >> 7;

  // GATHER==1 loop-invariant per-thread geometry
  int Gh[4], Gw[4], Gb[4], Gv[4];
  if (GATHER == 1) {
    #pragma unroll
    for (int l = 0; l < 4; ++l) {
      int gm = bm + am4[l];
      Gv[l] = (gm < M);
      int hw = gm & 4095;
      Gh[l] = hw >> 6; Gw[l] = hw & 63; Gb[l] = (gm >> 12) << 12;
    }
  }

  float4 pa[4], pb[2];
  float pa2[16];

  auto loadA = [&](int k0, int l) -> float4 {
    float4 v = make_float4(0.f, 0.f, 0.f, 0.f);
    int gm = bm + am4[l], gk = k0 + ak4[l];
    if (GATHER == 4) {
      if (gm < M) {
        const float* base = A + ((size_t)gm * 8) * DM + gk;
        float4 s = make_float4(0.f, 0.f, 0.f, 0.f);
        #pragma unroll
        for (int p = 0; p < 8; ++p) {
          float4 t = *reinterpret_cast<const float4*>(base + (size_t)p * DM);
          s.x += t.x; s.y += t.y; s.z += t.z; s.w += t.w;
        }
        v = make_float4(s.x * 0.125f, s.y * 0.125f, s.z * 0.125f, s.w * 0.125f);
      }
    } else {
      if (gm < M) {
        if (gk + 3 < K) v = *reinterpret_cast<const float4*>(A + (size_t)gm * lda + gk);
        else {
          float t[4] = {0.f, 0.f, 0.f, 0.f};
          #pragma unroll
          for (int e = 0; e < 4; ++e) if (gk + e < K) t[e] = A[(size_t)gm * lda + gk + e];
          v = make_float4(t[0], t[1], t[2], t[3]);
        }
      }
    }
    return v;
  };
  auto loadB = [&](int k0, int l) -> float4 {
    float4 v = make_float4(0.f, 0.f, 0.f, 0.f);
    int gn = bn + bn2[l], gk = k0 + bk2[l];
    if (gn < N) {
      if (gk + 3 < K) v = *reinterpret_cast<const float4*>(Bw + (size_t)gn * K + gk);
      else {
        float t[4] = {0.f, 0.f, 0.f, 0.f};
        #pragma unroll
        for (int e = 0; e < 4; ++e) if (gk + e < K) t[e] = Bw[(size_t)gn * K + gk + e];
        v = make_float4(t[0], t[1], t[2], t[3]);
      }
    }
    return v;
  };
  auto prefetch = [&](int k0) {
    if (GATHER == 2) {
      int gm = bm + m2;
      int b = gm >> 12, hw = gm & 4095;
      #pragma unroll
      for (int j = 0; j < 16; ++j) {
        int k = k0 + khalf * 16 + j;
        int i = k >> 2, t = k & 3;
        pa2[j] = A[(size_t)(((b << 2) + t) * CIN + i) * HWSZ + hw];
      }
    } else if (GATHER == 1) {
      // tap uniform per K-tile: BK=32 never straddles a 256-wide tap
      int tap = k0 >> 8;
      int ky = tap / 3, kx = tap - ky * 3;
      int c0 = k0 & 255;
      #pragma unroll
      for (int l = 0; l < 4; ++l) {
        float4 v = make_float4(0.f, 0.f, 0.f, 0.f);
        int hh = Gh[l] + ky - 1, ww = Gw[l] + kx - 1;
        if (Gv[l] && hh >= 0 && hh < 64 && ww >= 0 && ww < 64)
          v = *reinterpret_cast<const float4*>(
                A + (size_t)(Gb[l] + (hh << 6) + ww) * 256 + c0 + ak4[l]);
        pa[l] = v;
      }
    } else {
      #pragma unroll
      for (int l = 0; l < 4; ++l) pa[l] = loadA(k0, l);
    }
    #pragma unroll
    for (int l = 0; l < 2; ++l) pb[l] = loadB(k0, l);
  };

  auto storeTiles = [&](int buf) {
    uint32_t* SA = SAb + buf * 4096;
    uint32_t* SB = SBb + buf * 2048;
    if (GATHER == 2) {
      int tm = m2 >> 4, rr = m2 & 15;
      #pragma unroll
      for (int j = 0; j < 8; ++j) {
        int lw = (rr & 7) * 4 + (j & 3);
        int reg = (rr >> 3) | ((j >> 2) << 1);
        float h0, l0, h1, l1;
        split_bf16(pa2[2 * j], h0, l0);
        split_bf16(pa2[2 * j + 1], h1, l1);
        int s0 = (((tm * 2 + khalf) * 32 + lw) * 2) ^ ((lw >> 2) & 7);
        SA[s0 * 4 + reg]       = pack_bf16(h0, h1);
        SA[(s0 ^ 1) * 4 + reg] = pack_bf16(l0, l1);
      }
    } else {
      #pragma unroll
      for (int l = 0; l < 4; ++l) {
        float v[4] = {pa[l].x, pa[l].y, pa[l].z, pa[l].w};
        int tm = am4[l] >> 4, rr = am4[l] & 15;
        int tk = ak4[l] >> 4, k16b = ak4[l] & 15;
        #pragma unroll
        for (int e = 0; e < 2; ++e) {
          int k16p = k16b + 2 * e;
          int lw = (rr & 7) * 4 + ((k16p >> 1) & 3);
          int reg = (rr >> 3) | ((k16p >> 3) << 1);
          float h0, l0, h1, l1;
          split_bf16(v[2 * e], h0, l0);
          split_bf16(v[2 * e + 1], h1, l1);
          int s0 = (((tm * 2 + tk) * 32 + lw) * 2) ^ ((lw >> 2) & 7);
          SA[s0 * 4 + reg]       = pack_bf16(h0, h1);
          SA[(s0 ^ 1) * 4 + reg] = pack_bf16(l0, l1);
        }
      }
    }
    #pragma unroll
    for (int l = 0; l < 2; ++l) {
      float v[4] = {pb[l].x, pb[l].y, pb[l].z, pb[l].w};
      int ntile = bn2[l] >> 3, gidn = bn2[l] & 7;
      int np = ntile >> 1, nodd = ntile & 1;
      int tk = bk2[l] >> 4, k16b = bk2[l] & 15;
      #pragma unroll
      for (int e = 0; e < 2; ++e) {
        int k16p = k16b + 2 * e;
        int lw = gidn * 4 + ((k16p >> 1) & 3);
        int reg = k16p >> 3;
        int word = nodd * 2 + reg;
        float h0, l0, h1, l1;
        split_bf16(v[2 * e], h0, l0);
        split_bf16(v[2 * e + 1], h1, l1);
        int s0 = (((np * 2 + tk) * 32 + lw) * 2) ^ ((lw >> 2) & 7);
        SB[s0 * 4 + word]       = pack_bf16(h0, h1);
        SB[(s0 ^ 1) * 4 + word] = pack_bf16(l0, l1);
      }
    }
  };

  prefetch(0);
  storeTiles(0);
  if (BK < Kpad) prefetch(BK);
  __syncthreads();

  int cur = 0;
  for (int k0 = 0; k0 < Kpad; k0 += BK) {
    if (k0 + BK < Kpad) {
      storeTiles(cur ^ 1);
      if (k0 + 2 * BK < Kpad) prefetch(k0 + 2 * BK);
    }
    const uint32_t* SA = SAb + cur * 4096;
    const uint32_t* SB = SBb + cur * 2048;
    #pragma unroll
    for (int tk = 0; tk < 2; ++tk) {
      uint32_t Ahf[2][4], Alf[2][4];
      #pragma unroll
      for (int i = 0; i < 2; ++i) {
        int tm = (wm >> 4) + i;
        int s0 = (((tm * 2 + tk) * 32 + lane) * 2) ^ xr;
        *reinterpret_cast<uint4*>(Ahf[i]) = *reinterpret_cast<const uint4*>(&SA[s0 * 4]);
        *reinterpret_cast<uint4*>(Alf[i]) = *reinterpret_cast<const uint4*>(&SA[(s0 ^ 1) * 4]);
      }
      uint32_t Bhf[2][4], Blf[2][4];
      #pragma unroll
      for (int jp = 0; jp < 2; ++jp) {
        int np = (wn >> 4) + jp;
        int s0 = (((np * 2 + tk) * 32 + lane) * 2) ^ xr;
        *reinterpret_cast<uint4*>(Bhf[jp]) = *reinterpret_cast<const uint4*>(&SB[s0 * 4]);
        *reinterpret_cast<uint4*>(Blf[jp]) = *reinterpret_cast<const uint4*>(&SB[(s0 ^ 1) * 4]);
      }
      #pragma unroll
      for (int i = 0; i < 2; ++i)
        #pragma unroll
        for (int jp = 0; jp < 2; ++jp)
          #pragma unroll
          for (int nodd = 0; nodd < 2; ++nodd) {
            int j = jp * 2 + nodd;
            uint32_t bh[2] = {Bhf[jp][nodd * 2], Bhf[jp][nodd * 2 + 1]};
            uint32_t bl[2] = {Blf[jp][nodd * 2], Blf[jp][nodd * 2 + 1]};
            mma_bf16(acc[i][j], Ahf[i], bh);
            mma_bf16(acc[i][j], Ahf[i], bl);
            mma_bf16(acc[i][j], Alf[i], bh);
          }
    }
    __syncthreads();
    cur ^= 1;
  }

  #pragma unroll
  for (int i = 0; i < 2; ++i) {
    #pragma unroll
    for (int j = 0; j < 4; ++j) {
      int c0 = bn + wn + 8 * j + 2 * tig;
      #pragma unroll
      for (int half = 0; half < 2; ++half) {
        int gm = bm + wm + 16 * i + gid + 8 * half;
        if (gm >= M) continue;
        #pragma unroll
        for (int e = 0; e < 2; ++e) {
          int gn = c0 + e;
          if (gn >= N) continue;
          float v = acc[i][j][half * 2 + e] + (bias ? bias[gn] : 0.f);
          if (EPI == 1) v = fmaxf(v, 0.f);
          if (EPI == 2) v += res[(size_t)gm * N + gn];
          if (EPI == 3) {
            int hw = gm & 4095, h = hw >> 6, w = hw & 63;
            v += (gn < 128) ? aux[h * 128 + gn] : aux[8192 + w * 128 + (gn - 128)];
          }
          if (EPI == 5) { if (gn < 512) v = fmaxf(v, 0.f); }
          if (EPI == 6) {
            int b = (gm >= NQ) ? 1 : 0;
            int kq = gm - b * NQ;
            ((float*)res)[((size_t)(b * DM + gn)) * NQ + kq] = v;
          }
          C[(size_t)gm * N + gn] = v;
        }
      }
    }
  }
}

// ---------------------------------------------------------------------------
// Prologue mega-kernel: sections by blockIdx.x
//  [0,512)       wcomb + bcomb
//  [512,576)     sine pos tables
//  [576,2880)    w_sm permute
//  [2880,7488)   wcat: 6 layers x 768 rows [w_b1 ; w_r1 ; Wq_l] + bcat
//  [7488,8088)   qinit + boxes init
// ---------------------------------------------------------------------------
#define PRO_GRID 8088
__global__ __launch_bounds__(256)
void k_prologue(const float* __restrict__ w_tf, const float* __restrict__ w_in,
                const float* __restrict__ b_tf, const float* __restrict__ b_in,
                const float* __restrict__ w_sm,
                const float* __restrict__ w_b1, const float* __restrict__ b_b1,
                const float* __restrict__ w_r1, const float* __restrict__ b_r1,
                const float* __restrict__ Wq,  const float* __restrict__ bq,
                const float* __restrict__ q_embed, const float* __restrict__ q_pos,
                const float* __restrict__ boxes0,
                float* __restrict__ wcomb, float* __restrict__ bcomb,
                float* __restrict__ pos,   float* __restrict__ wsmp,
                float* __restrict__ wcat,  float* __restrict__ bcat,
                float* __restrict__ queries, float* __restrict__ boxes) {
  int blk = blockIdx.x, tid = threadIdx.x;
  if (blk < 512) {
    int idx = blk * 256 + tid;
    int dm = idx >> 9, k = idx & 511, i = k >> 2, t = k & 3;
    float s = 0.f;
    for (int c = 0; c < CIN; ++c) {
      const float* wt = w_tf + (c * CIN + i) * 3;
      float we = wt[1];
      if (t != 3) we += wt[0];
      if (t != 0) we += wt[2];
      s += w_in[dm * CIN + c] * we;
    }
    wcomb[idx] = 0.25f * s;
    if (idx < 256) {
      float sb = b_in[idx];
      for (int c = 0; c < CIN; ++c) sb += w_in[idx * CIN + c] * b_tf[c];
      bcomb[idx] = sb;
    }
  } else if (blk < 576) {
    int idx = (blk - 512) * 256 + tid;
    int half = idx >> 13;
    int r = idx & 8191;
    int hw = r >> 7, c = r & 127;
    float dim_t = powf(10000.f, 2.f * (float)(c >> 2) / 64.f);
    float v = (float)(hw + 1) / (64.f + 1e-6f) * 2.f * 3.14159265358979323846f;
    float a = v / dim_t;
    float o = (c & 1) ? cosf(a) : sinf(a);
    pos[half * 8192 + r] = o;
  } else if (blk < 2880) {
    int idx = (blk - 576) * 256 + tid;
    int o = idx / KP1, r = idx - o * KP1;
    int ky = r / 768, rem = r - ky * 768;
    int kx = rem >> 8, c = rem & 255;
    wsmp[idx] = w_sm[(size_t)o * KP1 + c * 9 + ky * 3 + kx];
  } else if (blk < 7488) {
    int r3 = blk - 2880;                    // 0..4607
    int l = r3 / 768, row = r3 - l * 768;
    const float* src;
    float bv;
    if (row < 256)      { src = w_b1 + (size_t)row * 256;                       bv = b_b1[row]; }
    else if (row < 512) { src = w_r1 + (size_t)(row - 256) * 256;               bv = b_r1[row - 256]; }
    else                { src = Wq + (size_t)l * 65536 + (size_t)(row - 512) * 256; bv = bq[l * 256 + row - 512]; }
    wcat[((size_t)l * 768 + row) * 256 + tid] = src[tid];
    if (tid == 0) bcat[l * 768 + row] = bv;
  } else {
    int m = blk - 7488;
    int q = m % NQ;
    queries[m * DM + tid] = q_embed[q * DM + tid] + q_pos[q * DM + tid];
    if (tid < 4) boxes[m * 4 + tid] = boxes0[m * 4 + tid];
  }
}

// ---------------------------------------------------------------------------
// Fused box-update + refpoints + bilinear patch sampling. grid=600, block=256.
// hhq layout per row: [hb(256) | h1(256) | qp(256)], stride 768.
// ---------------------------------------------------------------------------
__global__ __launch_bounds__(256)
void k_refsample(const float* __restrict__ hhq, float* __restrict__ boxes,
                 const float* __restrict__ w_r2, const float* __restrict__ b_r2,
                 const float* __restrict__ w_b2, const float* __restrict__ b_b2,
                 const float* __restrict__ f0, float* __restrict__ flat,
                 int do_update) {
  int m = blockIdx.x;
  int tid = threadIdx.x;
  __shared__ float ro_s[16];
  __shared__ float box_s[4];

  // phase 1: ro = tanh(h1 @ w_r2 + b)*0.5  (16 groups of 16)
  {
    int g = tid >> 4, lane16 = tid & 15;
    float s = 0.f;
    for (int d = lane16; d < DM; d += 16)
      s += hhq[m * 768 + 256 + d] * w_r2[g * DM + d];
    #pragma unroll
    for (int off = 8; off > 0; off >>= 1)
      s += __shfl_down_sync(0xffffffffu, s, off, 16);
    if (lane16 == 0) ro_s[g] = tanhf(s + b_r2[g]) * 0.5f;
  }
  // phase 2: box update from hb (4 groups of 32; warps 0-3)
  if (do_update) {
    int j = tid >> 5, lane = tid & 31;
    if (j < 4) {
      float s = 0.f;
      for (int d = lane; d < DM; d += 32)
        s += hhq[m * 768 + d] * w_b2[j * DM + d];
      #pragma unroll
      for (int off = 16; off > 0; off >>= 1)
        s += __shfl_down_sync(0xffffffffu, s, off);
      if (lane == 0) {
        float delta = 1.f / (1.f + expf(-(s + b_b2[j])));
        float nb = boxes[m * 4 + j] + 0.1f * tanhf(delta - 0.5f);
        nb = fminf(fmaxf(nb, 0.f), 1.f);
        boxes[m * 4 + j] = nb;
        box_s[j] = nb;
      }
    }
  } else {
    if (tid < 4) box_s[tid] = boxes[m * 4 + tid];
  }
  __syncthreads();

  __shared__ float ref_s[8][2];
  if (tid < 16) {
    int p = tid >> 1, j = tid & 1;
    float v = box_s[j] + ro_s[p * 2 + j];
    ref_s[p][j] = fminf(fmaxf(v, 0.f), 1.f);
  }
  __syncthreads();

  int b = (m >= NQ) ? 1 : 0;
  const float* f = f0 + (size_t)b * HWSZ * DM;
  int c = tid;
  float* outm = flat + (size_t)m * 8 * KP1;
  #pragma unroll 1
  for (int p = 0; p < 8; ++p) {
    float rx = ref_s[p][0], ry = ref_s[p][1];
    float* outp = outm + (size_t)p * KP1;
    #pragma unroll 1
    for (int kk = 0; kk < 9; ++kk) {
      float oy = (float)(kk / 3 - 1), ox = (float)(kk % 3 - 1);
      float x = fminf(fmaxf((rx + ox * (1.f / 64.f)) * 63.f, 0.f), 63.f);
      float y = fminf(fmaxf((ry + oy * (1.f / 64.f)) * 63.f, 0.f), 63.f);
      float x0 = floorf(x), y0 = floorf(y);
      float wx = x - x0, wy = y - y0;
      int x0i = (int)x0, y0i = (int)y0;
      int x1i = min(x0i + 1, 63), y1i = min(y0i + 1, 63);
      float v00 = f[((y0i << 6) + x0i) * DM + c];
      float v01 = f[((y0i << 6) + x1i) * DM + c];
      float v10 = f[((y1i << 6) + x0i) * DM + c];
      float v11 = f[((y1i << 6) + x1i) * DM + c];
      float v = v00 * (1.f - wx) * (1.f - wy) + v01 * wx * (1.f - wy)
              + v10 * (1.f - wx) * wy + v11 * wx * wy;
      outp[kk * 256 + c] = v;
    }
  }
}

__global__ __launch_bounds__(512)
void k_softmax(float* __restrict__ S) {
  int m = blockIdx.x;
  int b = (m >= NQ) ? 1 : 0;
  float* row = S + (size_t)b * NQ * NQ + (size_t)(m - b * NQ) * NQ;
  int t = threadIdx.x;
  __shared__ float red[512];
  float v = (t < NQ) ? row[t] * 0.0625f : -1e30f;
  red[t] = v; __syncthreads();
  for (int s = 256; s > 0; s >>= 1) { if (t < s) red[t] = fmaxf(red[t], red[t + s]); __syncthreads(); }
  float mx = red[0]; __syncthreads();
  float e = (t < NQ) ? expf(v - mx) : 0.f;
  red[t] = e; __syncthreads();
  for (int s = 256; s > 0; s >>= 1) { if (t < s) red[t] += red[t + s]; __syncthreads(); }
  float inv = 1.f / red[0];
  if (t < NQ) row[t] = e * inv;
}

// Final: block m: logits + final box update (uses hb from q_final)
__global__ __launch_bounds__(256)
void k_final(const float* __restrict__ queries, const float* __restrict__ w_cls,
             const float* __restrict__ b_cls, const float* __restrict__ hb,
             const float* __restrict__ w_b2, const float* __restrict__ b_b2,
             const float* __restrict__ boxes, float* __restrict__ out) {
  int m = blockIdx.x, t = threadIdx.x;
  __shared__ float red[256];
  red[t] = queries[m * DM + t] * w_cls[t];
  // box update: 4 groups of 32 (warps 4-7 idle in reduction below anyway)
  int j = t >> 5, lane = t & 31;
  float s = 0.f;
  if (j < 4) {
    for (int d = lane; d < DM; d += 32) s += hb[m * DM + d] * w_b2[j * DM + d];
    #pragma unroll
    for (int off = 16; off > 0; off >>= 1) s += __shfl_down_sync(0xffffffffu, s, off);
    if (lane == 0) {
      float delta = 1.f / (1.f + expf(-(s + b_b2[j])));
      float nb = boxes[m * 4 + j] + 0.1f * tanhf(delta - 0.5f);
      out[MQ + m * 4 + j] = fminf(fmaxf(nb, 0.f), 1.f);
    }
  }
  __syncthreads();
  for (int st = 128; st > 0; st >>= 1) { if (t < st) red[t] += red[t + st]; __syncthreads(); }
  if (t == 0) out[m] = red[0] + b_cls[0];
}

// ---------------------------------------------------------------------------
static inline dim3 ggrid(int M, int N, int Z = 1) {
  return dim3((N + 63) / 64, (M + 127) / 128, Z);
}
#define GSMEM 49152

extern "C" void kernel_launch(void* const* d_in, const int* in_sizes, int n_in,
                              void* d_out, int out_size) {
  const float* feat   = (const float*)d_in[0];
  const float* boxes0 = (const float*)d_in[1];
  const float* w_tf   = (const float*)d_in[2];
  const float* b_tf   = (const float*)d_in[3];
  const float* w_in   = (const float*)d_in[4];
  const float* b_in   = (const float*)d_in[5];
  const float* w_lat  = (const float*)d_in[6];
  const float* b_lat  = (const float*)d_in[7];
  const float* w_sm   = (const float*)d_in[8];
  const float* b_sm   = (const float*)d_in[9];
  const float* q_embed= (const float*)d_in[10];
  const float* q_pos  = (const float*)d_in[11];
  const float* Wq     = (const float*)d_in[12];
  const float* bq     = (const float*)d_in[13];
  const float* Wo     = (const float*)d_in[14];
  const float* bo     = (const float*)d_in[15];
  const float* Wp1    = (const float*)d_in[16];
  const float* bp1    = (const float*)d_in[17];
  const float* Wp2    = (const float*)d_in[18];
  const float* bp2    = (const float*)d_in[19];
  const float* w_r1   = (const float*)d_in[20];
  const float* b_r1   = (const float*)d_in[21];
  const float* w_r2   = (const float*)d_in[22];
  const float* b_r2   = (const float*)d_in[23];
  const float* w_b1   = (const float*)d_in[24];
  const float* b_b1   = (const float*)d_in[25];
  const float* w_b2   = (const float*)d_in[26];
  const float* b_b2   = (const float*)d_in[27];
  const float* w_cls  = (const float*)d_in[28];
  const float* b_cls  = (const float*)d_in[29];
  float* out = (float*)d_out;

  static bool attr_done = false;
  if (!attr_done) {
    cudaFuncSetAttribute(gemm_b16<0,0>, cudaFuncAttributeMaxDynamicSharedMemorySize, GSMEM);
    cudaFuncSetAttribute(gemm_b16<1,0>, cudaFuncAttributeMaxDynamicSharedMemorySize, GSMEM);
    cudaFuncSetAttribute(gemm_b16<2,0>, cudaFuncAttributeMaxDynamicSharedMemorySize, GSMEM);
    cudaFuncSetAttribute(gemm_b16<0,1>, cudaFuncAttributeMaxDynamicSharedMemorySize, GSMEM);
    cudaFuncSetAttribute(gemm_b16<3,2>, cudaFuncAttributeMaxDynamicSharedMemorySize, GSMEM);
    cudaFuncSetAttribute(gemm_b16<5,0>, cudaFuncAttributeMaxDynamicSharedMemorySize, GSMEM);
    cudaFuncSetAttribute(gemm_b16<6,4>, cudaFuncAttributeMaxDynamicSharedMemorySize, GSMEM);
    attr_done = true;
  }

  float* base = nullptr;
  cudaGetSymbolAddress((void**)&base, g_buf);
  float* p_wcomb = base + O_WCOMB;
  float* p_bcomb = base + O_BCOMB;
  float* p_py    = base + O_PY;     // px contiguous at +8192
  float* p_wsmp  = base + O_WSMP;
  float* p_wcat  = base + O_WCAT;
  float* p_bcat  = base + O_BCAT;
  float* p_x     = base + O_X;
  float* p_lat   = base + O_LAT;
  float* p_f0    = base + O_F0;
  float* p_q     = base + O_Q;
  float* p_hhq   = base + O_HHQ;
  float* p_flat  = base + O_FLAT;
  float* p_pv    = base + O_PV;
  float* p_kv    = base + O_KV;
  float* p_kvT   = base + O_KVT;
  float* p_S     = base + O_S;
  float* p_ao    = base + O_AO;
  float* p_hb    = base + O_HB;
  float* p_box   = base + O_BOX;

  // ---- single prologue launch ----
  k_prologue<<<PRO_GRID, 256>>>(w_tf, w_in, b_tf, b_in, w_sm,
                                w_b1, b_b1, w_r1, b_r1, Wq, bq,
                                q_embed, q_pos, boxes0,
                                p_wcomb, p_bcomb, p_py, p_wsmp,
                                p_wcat, p_bcat, p_q, p_box);

  // ---- stem: fused conv3d+mean_T+in-proj GEMM, +pos epi ----
  gemm_b16<3,2><<<ggrid(MROWS, DM), 256, GSMEM>>>(feat, p_wcomb, p_bcomb, nullptr, p_py,
                                                  p_x, MROWS, DM, 512, 512, 0, 0, 0);

  // ---- scale-1 feature ----
  gemm_b16<0,0><<<ggrid(MROWS, DM), 256, GSMEM>>>(p_x, w_lat, b_lat, nullptr, nullptr,
                                                  p_lat, MROWS, DM, DM, DM, 0, 0, 0);
  gemm_b16<0,1><<<ggrid(MROWS, DM), 256, GSMEM>>>(p_lat, p_wsmp, b_sm, nullptr, nullptr,
                                                  p_f0, MROWS, DM, KP1, KP1, 0, 0, 0);

  for (int l = 0; l < NLAY; ++l) {
    const float* Wo_l  = Wo  + (size_t)l * DM * DM;
    const float* bo_l  = bo  + (size_t)l * DM;
    const float* Wp1_l = Wp1 + (size_t)l * DM * KP1;
    const float* bp1_l = bp1 + (size_t)l * DM;
    const float* Wp2_l = Wp2 + (size_t)l * DM * DM;
    const float* bp2_l = bp2 + (size_t)l * DM;

    // merged [hb | h1 | qp] GEMM: N=768, relu on gn<512
    gemm_b16<5,0><<<ggrid(MQ, 768), 256, GSMEM>>>(p_q, p_wcat + (size_t)l * 768 * 256,
                                                  p_bcat + (size_t)l * 768, nullptr, nullptr,
                                                  p_hhq, MQ, 768, DM, DM, 0, 0, 0);

    // fused box-update + refpoints + sampling
    k_refsample<<<MQ, 256>>>(p_hhq, p_box, w_r2, b_r2, w_b2, b_b2,
                             p_f0, p_flat, l > 0 ? 1 : 0);

    gemm_b16<1,0><<<ggrid(MS, DM), 256, GSMEM>>>(p_flat, Wp1_l, bp1_l, nullptr, nullptr,
                                                 p_pv, MS, DM, KP1, KP1, 0, 0, 0);
    gemm_b16<6,4><<<ggrid(MQ, DM), 256, GSMEM>>>(p_pv, Wp2_l, bp2_l, p_kvT, nullptr,
                                                 p_kv, MQ, DM, DM, DM, 0, 0, 0);

    // attention
    gemm_b16<0,0><<<ggrid(NQ, NQ, BATCH), 256, GSMEM>>>(p_hhq + 512, p_kv, nullptr, nullptr, nullptr,
                                                        p_S, NQ, NQ, DM, 768,
                                                        (long long)NQ * 768, (long long)NQ * DM,
                                                        (long long)NQ * NQ);
    k_softmax<<<MQ, 512>>>(p_S);
    gemm_b16<0,0><<<ggrid(NQ, DM, BATCH), 256, GSMEM>>>(p_S, p_kvT, nullptr, nullptr, nullptr,
                                                        p_ao, NQ, DM, NQ, NQ,
                                                        (long long)NQ * NQ, (long long)DM * NQ,
                                                        (long long)NQ * DM);
    gemm_b16<2,0><<<ggrid(MQ, DM), 256, GSMEM>>>(p_ao, Wo_l, bo_l, p_q, nullptr,
                                                 p_q, MQ, DM, DM, DM, 0, 0, 0);
  }

  // final box-head hb from q_final, then fused logits + final box update
  gemm_b16<1,0><<<ggrid(MQ, DM), 256, GSMEM>>>(p_q, w_b1, b_b1, nullptr, nullptr,
                                               p_hb, MQ, DM, DM, DM, 0, 0, 0);
  k_final<<<MQ, 256>>>(p_q, w_cls, b_cls, p_hb, w_b2, b_b2, p_box, out);
}